// round 1
// baseline (speedup 1.0000x reference)
#include <cuda_runtime.h>
#include <cuda_bf16.h>
#include <math.h>

// ---------------- Problem constants ----------------
#define Bn   2
#define Sn   2048
#define HIDn 2048
#define NHn  16
#define NKVn 4
#define DHn  128
#define GRP  (NHn / NKVn)        // 4
#define BSn  (Bn * Sn)           // 4096
#define QDIM (NHn * DHn)         // 2048
#define KVDIM (NKVn * DHn)       // 512

// ---------------- Scratch (device globals; no allocation allowed) ----------------
__device__ float g_Q[(size_t)BSn * QDIM];          // 4096 x 2048
__device__ float g_K[(size_t)BSn * KVDIM];         // 4096 x 512
__device__ float g_V[(size_t)BSn * KVDIM];         // 4096 x 512
__device__ float g_Scores[(size_t)Bn * NHn * Sn * Sn];  // 32 x 2048 x 2048 (512 MB)
__device__ float g_Attn[(size_t)BSn * QDIM];       // 4096 x 2048

// ---------------- SGEMM: 128x128 tile, BK=8, 256 threads, 8x8 per thread ----------------
// mode 0: plain C = alpha * A @ B(^T)        (z-batch via linear strides sA/sB/sC)
// mode 1: scores  = alpha * Q @ K^T  + causal mask(-1e9), z = b*NH + h (GQA decode)
// mode 2: attnout = P @ V,                    z = b*NH + h (GQA decode)
template <bool TRANSB>
__global__ void __launch_bounds__(256, 2)
sgemm_kernel(const float* __restrict__ A0, const float* __restrict__ B0,
             float* __restrict__ C0,
             int M, int N, int K, int lda, int ldb, int ldc,
             long sA, long sB, long sC,
             int mode, float alpha)
{
    const int z = blockIdx.z;
    const float* A;
    const float* B;
    float* C;
    if (mode == 1) {
        int b = z >> 4, h = z & 15;
        A = A0 + (long)b * Sn * QDIM + (long)h * DHn;          // Q[b,:,h,:]
        B = B0 + (long)b * Sn * KVDIM + (long)(h >> 2) * DHn;  // K[b,:,h/4,:]
        C = C0 + (long)z * Sn * Sn;
    } else if (mode == 2) {
        int b = z >> 4, h = z & 15;
        A = A0 + (long)z * Sn * Sn;                            // probs[b,h]
        B = B0 + (long)b * Sn * KVDIM + (long)(h >> 2) * DHn;  // V[b,:,h/4,:]
        C = C0 + (long)b * Sn * QDIM + (long)h * DHn;          // attn[b,:,h,:]
    } else {
        A = A0 + (long)z * sA;
        B = B0 + (long)z * sB;
        C = C0 + (long)z * sC;
    }

    __shared__ float As[8][128];
    __shared__ float Bs[8][128];

    const int tid  = threadIdx.x;
    const int row0 = blockIdx.y * 128;
    const int col0 = blockIdx.x * 128;

    // A tile load mapping: 128 rows x 8 cols; each thread one float4
    const int arow = tid >> 1;
    const int acol = (tid & 1) * 4;
    // B (NN) mapping: 8 rows x 128 cols
    const int bkr  = tid >> 5;          // 0..7
    const int bnc  = (tid & 31) * 4;    // 0..124
    // B (NT) mapping: 128 n-rows x 8 k-cols
    const int ntr  = tid >> 1;
    const int ntk  = (tid & 1) * 4;

    const int ty = tid >> 4;            // 0..15 -> rows ty*8 .. +7
    const int tx = tid & 15;            // 0..15 -> cols tx*8 .. +7

    float acc[8][8];
    #pragma unroll
    for (int i = 0; i < 8; i++)
        #pragma unroll
        for (int j = 0; j < 8; j++)
            acc[i][j] = 0.0f;

    for (int k0 = 0; k0 < K; k0 += 8) {
        // Load A tile (transposed into As[k][m])
        float4 av = *(const float4*)(A + (long)(row0 + arow) * lda + k0 + acol);
        As[acol + 0][arow] = av.x;
        As[acol + 1][arow] = av.y;
        As[acol + 2][arow] = av.z;
        As[acol + 3][arow] = av.w;

        if (!TRANSB) {
            float4 bv = *(const float4*)(B + (long)(k0 + bkr) * ldb + col0 + bnc);
            *(float4*)&Bs[bkr][bnc] = bv;
        } else {
            float4 bv = *(const float4*)(B + (long)(col0 + ntr) * ldb + k0 + ntk);
            Bs[ntk + 0][ntr] = bv.x;
            Bs[ntk + 1][ntr] = bv.y;
            Bs[ntk + 2][ntr] = bv.z;
            Bs[ntk + 3][ntr] = bv.w;
        }
        __syncthreads();

        #pragma unroll
        for (int k = 0; k < 8; k++) {
            float af[8], bf[8];
            *(float4*)&af[0] = *(const float4*)&As[k][ty * 8 + 0];
            *(float4*)&af[4] = *(const float4*)&As[k][ty * 8 + 4];
            *(float4*)&bf[0] = *(const float4*)&Bs[k][tx * 8 + 0];
            *(float4*)&bf[4] = *(const float4*)&Bs[k][tx * 8 + 4];
            #pragma unroll
            for (int i = 0; i < 8; i++)
                #pragma unroll
                for (int j = 0; j < 8; j++)
                    acc[i][j] = fmaf(af[i], bf[j], acc[i][j]);
        }
        __syncthreads();
    }

    // Epilogue
    #pragma unroll
    for (int i = 0; i < 8; i++) {
        int gi = row0 + ty * 8 + i;
        #pragma unroll
        for (int j = 0; j < 8; j++) {
            int gj = col0 + tx * 8 + j;
            float v = acc[i][j];
            if (mode == 1) {
                v *= alpha;
                if (gj > gi) v -= 1.0e9f;   // causal mask, matches reference's +(-1e9)
            } else if (mode == 0) {
                v *= alpha;
            }
            C[(long)gi * ldc + gj] = v;
        }
    }
}

// ---------------- Fused RMSNorm + RoPE (one warp per (b,s,h) head vector) ----------------
__global__ void norm_rope_kernel(float* __restrict__ x, const float* __restrict__ w,
                                 const float* __restrict__ cosp, const float* __restrict__ sinp,
                                 int nheads)
{
    int warp = (blockIdx.x * blockDim.x + threadIdx.x) >> 5;
    int lane = threadIdx.x & 31;
    int total = BSn * nheads;
    if (warp >= total) return;
    int h  = warp % nheads;
    int bs = warp / nheads;
    int s  = bs & (Sn - 1);

    float* row = x + (long)bs * nheads * DHn + (long)h * DHn;
    float v0 = row[lane];
    float v1 = row[lane + 32];
    float v2 = row[lane + 64];
    float v3 = row[lane + 96];

    float ss = v0 * v0 + v1 * v1 + v2 * v2 + v3 * v3;
    #pragma unroll
    for (int o = 16; o > 0; o >>= 1) ss += __shfl_xor_sync(0xFFFFFFFFu, ss, o);
    float r = rsqrtf(ss * (1.0f / 128.0f) + 1e-6f);

    v0 = v0 * r * w[lane];
    v1 = v1 * r * w[lane + 32];
    v2 = v2 * r * w[lane + 64];
    v3 = v3 * r * w[lane + 96];

    const float* cs = cosp + (long)s * DHn;
    const float* sn = sinp + (long)s * DHn;
    // rotate_half: out[d] = x[d]*cos[d] - x[d+64]*sin[d]     (d < 64)
    //              out[d] = x[d]*cos[d] + x[d-64]*sin[d]     (d >= 64)
    float o0 = v0 * cs[lane]      - v2 * sn[lane];
    float o1 = v1 * cs[lane + 32] - v3 * sn[lane + 32];
    float o2 = v2 * cs[lane + 64] + v0 * sn[lane + 64];
    float o3 = v3 * cs[lane + 96] + v1 * sn[lane + 96];

    row[lane]      = o0;
    row[lane + 32] = o1;
    row[lane + 64] = o2;
    row[lane + 96] = o3;
}

// ---------------- Row softmax over S=2048 columns ----------------
__global__ void softmax_kernel(float* __restrict__ scores)
{
    __shared__ float red[8];
    long row = blockIdx.x;
    float* p = scores + row * Sn;
    int tid = threadIdx.x;            // 256 threads
    int lane = tid & 31, wid = tid >> 5;

    float v[8];
    float m = -INFINITY;
    #pragma unroll
    for (int i = 0; i < 8; i++) {
        v[i] = p[tid + i * 256];
        m = fmaxf(m, v[i]);
    }
    #pragma unroll
    for (int o = 16; o > 0; o >>= 1) m = fmaxf(m, __shfl_xor_sync(0xFFFFFFFFu, m, o));
    if (lane == 0) red[wid] = m;
    __syncthreads();
    m = red[lane & 7];
    #pragma unroll
    for (int o = 4; o > 0; o >>= 1) m = fmaxf(m, __shfl_xor_sync(0xFFFFFFFFu, m, o));

    float s = 0.0f;
    #pragma unroll
    for (int i = 0; i < 8; i++) {
        v[i] = expf(v[i] - m);
        s += v[i];
    }
    #pragma unroll
    for (int o = 16; o > 0; o >>= 1) s += __shfl_xor_sync(0xFFFFFFFFu, s, o);
    if (lane == 0) red[wid] = s;
    __syncthreads();
    s = red[lane & 7];
    #pragma unroll
    for (int o = 4; o > 0; o >>= 1) s += __shfl_xor_sync(0xFFFFFFFFu, s, o);
    float inv = 1.0f / s;
    #pragma unroll
    for (int i = 0; i < 8; i++)
        p[tid + i * 256] = v[i] * inv;
}

// ---------------- Launch ----------------
extern "C" void kernel_launch(void* const* d_in, const int* in_sizes, int n_in,
                              void* d_out, int out_size)
{
    (void)in_sizes; (void)n_in; (void)out_size;
    const float* X    = (const float*)d_in[0];   // hidden_states [B,S,HID]
    const float* cosp = (const float*)d_in[2];   // [1,S,1,DH]
    const float* sinp = (const float*)d_in[3];
    const float* Wq   = (const float*)d_in[4];
    const float* Wk   = (const float*)d_in[5];
    const float* Wv   = (const float*)d_in[6];
    const float* Wo   = (const float*)d_in[7];
    const float* qw   = (const float*)d_in[8];
    const float* kw   = (const float*)d_in[9];
    float* out = (float*)d_out;

    void *Qp, *Kp, *Vp, *Sp, *Ap;
    cudaGetSymbolAddress(&Qp, g_Q);
    cudaGetSymbolAddress(&Kp, g_K);
    cudaGetSymbolAddress(&Vp, g_V);
    cudaGetSymbolAddress(&Sp, g_Scores);
    cudaGetSymbolAddress(&Ap, g_Attn);
    float* Q = (float*)Qp;
    float* K = (float*)Kp;
    float* V = (float*)Vp;
    float* S = (float*)Sp;
    float* A = (float*)Ap;

    const float scale = 0.08838834764831845f;   // 1/sqrt(128)

    // 1) Projections
    sgemm_kernel<false><<<dim3(QDIM / 128, BSn / 128, 1), 256>>>(
        X, Wq, Q, BSn, QDIM, HIDn, HIDn, QDIM, QDIM, 0, 0, 0, 0, 1.0f);
    sgemm_kernel<false><<<dim3(KVDIM / 128, BSn / 128, 1), 256>>>(
        X, Wk, K, BSn, KVDIM, HIDn, HIDn, KVDIM, KVDIM, 0, 0, 0, 0, 1.0f);
    sgemm_kernel<false><<<dim3(KVDIM / 128, BSn / 128, 1), 256>>>(
        X, Wv, V, BSn, KVDIM, HIDn, HIDn, KVDIM, KVDIM, 0, 0, 0, 0, 1.0f);

    // 2) RMSNorm + RoPE (warp per head-row)
    norm_rope_kernel<<<(BSn * NHn) / 8, 256>>>(Q, qw, cosp, sinp, NHn);
    norm_rope_kernel<<<(BSn * NKVn) / 8, 256>>>(K, kw, cosp, sinp, NKVn);

    // 3) Scores = scale * Q @ K^T + causal mask   (32 batches of 2048x2048x128)
    sgemm_kernel<true><<<dim3(Sn / 128, Sn / 128, Bn * NHn), 256>>>(
        Q, K, S, Sn, Sn, DHn, QDIM, KVDIM, Sn, 0, 0, 0, 1, scale);

    // 4) Softmax rows
    softmax_kernel<<<Bn * NHn * Sn, 256>>>(S);

    // 5) attn = P @ V   (32 batches of 2048x128x2048)
    sgemm_kernel<false><<<dim3(DHn / 128, Sn / 128, Bn * NHn), 256>>>(
        S, V, A, Sn, DHn, Sn, Sn, KVDIM, QDIM, 0, 0, 0, 2, 1.0f);

    // 6) Output projection
    sgemm_kernel<false><<<dim3(HIDn / 128, BSn / 128, 1), 256>>>(
        A, Wo, out, BSn, HIDn, QDIM, QDIM, HIDn, HIDn, 0, 0, 0, 0, 1.0f);
}

// round 3
// speedup vs baseline: 2.8697x; 2.8697x over previous
#include <cuda_runtime.h>
#include <cuda_bf16.h>
#include <math.h>
#include <stdint.h>

// ---------------- Problem constants ----------------
#define Bn   2
#define Sn   2048
#define HIDn 2048
#define NHn  16
#define NKVn 4
#define DHn  128
#define BSn  (Bn * Sn)           // 4096
#define QDIM (NHn * DHn)         // 2048
#define KVDIM (NKVn * DHn)       // 512

typedef __nv_bfloat16 bf16;

// ---------------- PTX helpers (base ISA only: sm_80+) ----------------
__device__ __forceinline__ uint32_t smem_u32(const void* p) {
    uint32_t a;
    asm("{ .reg .u64 t; cvta.to.shared.u64 t, %1; cvt.u32.u64 %0, t; }" : "=r"(a) : "l"(p));
    return a;
}

__device__ __forceinline__ void cp_async16(uint32_t saddr, const void* gaddr) {
    asm volatile("cp.async.cg.shared.global [%0], [%1], 16;" :: "r"(saddr), "l"(gaddr));
}
__device__ __forceinline__ void cp_commit() {
    asm volatile("cp.async.commit_group;" ::: "memory");
}
template <int N>
__device__ __forceinline__ void cp_wait() {
    asm volatile("cp.async.wait_group %0;" :: "n"(N) : "memory");
}

__device__ __forceinline__ void ldmat4(uint32_t* r, uint32_t addr) {
    asm volatile("ldmatrix.sync.aligned.m8n8.x4.shared.b16 {%0,%1,%2,%3}, [%4];"
                 : "=r"(r[0]), "=r"(r[1]), "=r"(r[2]), "=r"(r[3]) : "r"(addr));
}

__device__ __forceinline__ void mma16816(float* c, const uint32_t* a, const uint32_t* b) {
    asm volatile("mma.sync.aligned.m16n8k16.row.col.f32.bf16.bf16.f32 "
                 "{%0,%1,%2,%3}, {%4,%5,%6,%7}, {%8,%9}, {%0,%1,%2,%3};"
                 : "+f"(c[0]), "+f"(c[1]), "+f"(c[2]), "+f"(c[3])
                 : "r"(a[0]), "r"(a[1]), "r"(a[2]), "r"(a[3]), "r"(b[0]), "r"(b[1]));
}

// ---------------- Scratch (device globals) ----------------
__device__ __align__(256) float g_Q[(size_t)BSn * QDIM];
__device__ __align__(256) float g_K[(size_t)BSn * KVDIM];
__device__ __align__(256) float g_V[(size_t)BSn * KVDIM];
__device__ __align__(256) float g_S[(size_t)Bn * NHn * Sn * Sn];
__device__ __align__(256) float g_A[(size_t)BSn * QDIM];

__device__ __align__(256) bf16 g_Xh[(size_t)BSn * HIDn];
__device__ __align__(256) bf16 g_Xl[(size_t)BSn * HIDn];
__device__ __align__(256) bf16 g_Wqh[(size_t)QDIM * HIDn];
__device__ __align__(256) bf16 g_Wql[(size_t)QDIM * HIDn];
__device__ __align__(256) bf16 g_Wkh[(size_t)KVDIM * HIDn];
__device__ __align__(256) bf16 g_Wkl[(size_t)KVDIM * HIDn];
__device__ __align__(256) bf16 g_Wvh[(size_t)KVDIM * HIDn];
__device__ __align__(256) bf16 g_Wvl[(size_t)KVDIM * HIDn];
__device__ __align__(256) bf16 g_Woh[(size_t)HIDn * QDIM];
__device__ __align__(256) bf16 g_Wol[(size_t)HIDn * QDIM];
__device__ __align__(256) bf16 g_Qh[(size_t)BSn * QDIM];
__device__ __align__(256) bf16 g_Ql[(size_t)BSn * QDIM];
__device__ __align__(256) bf16 g_Kh[(size_t)BSn * KVDIM];
__device__ __align__(256) bf16 g_Kl[(size_t)BSn * KVDIM];
__device__ __align__(256) bf16 g_Vth[(size_t)Bn * KVDIM * Sn];
__device__ __align__(256) bf16 g_Vtl[(size_t)Bn * KVDIM * Sn];
__device__ __align__(256) bf16 g_Ph[(size_t)Bn * NHn * Sn * Sn];
__device__ __align__(256) bf16 g_Pl[(size_t)Bn * NHn * Sn * Sn];
__device__ __align__(256) bf16 g_Ah[(size_t)BSn * QDIM];
__device__ __align__(256) bf16 g_Al[(size_t)BSn * QDIM];

// ---------------- Split-bf16 mma.sync GEMM ----------------
// C[M,N] = alpha * (Ah+Al)[M,K] @ (Bh+Bl)[N,K]^T   (both K-major)
// mode 0: plain   mode 1: scores (GQA decode, causal tile skip)
// mode 2: P@V (GQA decode, K clipped to row0+128)
// Tile 128x128, BK=32, 256 thr, warp grid 2m x 4n (64x32/warp),
// 2-stage cp.async double buffer, padded smem pitch 80B (conflict-free ldmatrix).
#define PITCHB   80
#define TILE_B   (128 * PITCHB)       // 10240
#define OFF_AH   0
#define OFF_AL   (TILE_B)
#define OFF_BH   (2 * TILE_B)
#define OFF_BL   (3 * TILE_B)
#define STAGE_B  (4 * TILE_B)         // 40960
#define SMEM_BYTES (2 * STAGE_B)      // 81920

__global__ void __launch_bounds__(256, 1)
gemm_split(const bf16* __restrict__ Ah_, const bf16* __restrict__ Al_,
           const bf16* __restrict__ Bh_, const bf16* __restrict__ Bl_,
           float* __restrict__ C_,
           int lda, int ldb, int ldc, int K, int mode, float alpha)
{
    extern __shared__ __align__(128) char smem[];
    const int row0 = blockIdx.y * 128;
    const int col0 = blockIdx.x * 128;
    if (mode == 1 && col0 > row0) return;   // fully-masked causal tile

    const bf16* Ah = Ah_;
    const bf16* Al = Al_;
    const bf16* Bh = Bh_;
    const bf16* Bl = Bl_;
    float* C = C_;
    int Keff = K;
    if (mode == 1) {
        int b = blockIdx.z >> 4, h = blockIdx.z & 15;
        size_t ao = (size_t)b * Sn * QDIM + (size_t)h * DHn;
        size_t bo = (size_t)b * Sn * KVDIM + (size_t)(h >> 2) * DHn;
        Ah += ao; Al += ao; Bh += bo; Bl += bo;
        C += (size_t)blockIdx.z * Sn * Sn;
    } else if (mode == 2) {
        int b = blockIdx.z >> 4, h = blockIdx.z & 15;
        size_t ao = (size_t)blockIdx.z * Sn * Sn;
        size_t bo = ((size_t)b * NKVn + (size_t)(h >> 2)) * DHn * Sn;
        Ah += ao; Al += ao; Bh += bo; Bl += bo;
        C += (size_t)b * Sn * QDIM + (size_t)h * DHn;
        Keff = row0 + 128;                  // causal prefix
    }

    const int tid  = threadIdx.x;
    const int lane = tid & 31;
    const int warp = tid >> 5;
    const int wm   = warp >> 2;             // 0..1  -> m offset wm*64
    const int wn   = warp & 3;              // 0..3  -> n offset wn*32

    float acc[4][4][4];
    #pragma unroll
    for (int i = 0; i < 4; i++)
        #pragma unroll
        for (int j = 0; j < 4; j++)
            #pragma unroll
            for (int q = 0; q < 4; q++)
                acc[i][j][q] = 0.0f;

    const uint32_t sbase = smem_u32(smem);
    const int nch = Keff >> 5;

    // ---- stage loader: 4 tiles x 128 rows x 2 x 16B chunks ----
    auto load_stage = [&](int buf, int k0) {
        char* st = smem + buf * STAGE_B;
        #pragma unroll
        for (int ii = 0; ii < 2; ii++) {
            int i = tid + ii * 256;         // 0..511
            int r = i >> 2, c = i & 3;      // row, 16B-chunk (4 per 64B row)
            uint32_t dof = (uint32_t)(r * PITCHB + c * 16);
            size_t ga = (size_t)(row0 + r) * lda + k0 + c * 8;
            size_t gb = (size_t)(col0 + r) * ldb + k0 + c * 8;
            cp_async16(smem_u32(st + OFF_AH + dof), Ah + ga);
            cp_async16(smem_u32(st + OFF_AL + dof), Al + ga);
            cp_async16(smem_u32(st + OFF_BH + dof), Bh + gb);
            cp_async16(smem_u32(st + OFF_BL + dof), Bl + gb);
        }
        cp_commit();
    };

    load_stage(0, 0);

    for (int ch = 0; ch < nch; ch++) {
        if (ch + 1 < nch) {
            load_stage((ch + 1) & 1, (ch + 1) << 5);
            cp_wait<1>();
        } else {
            cp_wait<0>();
        }
        __syncthreads();

        const uint32_t st = sbase + (uint32_t)((ch & 1) * STAGE_B);

        #pragma unroll
        for (int kk = 0; kk < 32; kk += 16) {
            uint32_t ah[4][4], al[4][4];
            #pragma unroll
            for (int ma = 0; ma < 4; ma++) {
                uint32_t arow = (uint32_t)(wm * 64 + ma * 16 + (lane & 15));
                uint32_t acol = (uint32_t)((kk + ((lane >> 4) << 3)) * 2);
                ldmat4(ah[ma], st + OFF_AH + arow * PITCHB + acol);
                ldmat4(al[ma], st + OFF_AL + arow * PITCHB + acol);
            }
            uint32_t bh[4][2], bl[4][2];
            #pragma unroll
            for (int nb = 0; nb < 2; nb++) {
                uint32_t brow = (uint32_t)(wn * 32 + nb * 16 + ((lane >> 4) << 3) + (lane & 7));
                uint32_t bcol = (uint32_t)((kk + (((lane >> 3) & 1) << 3)) * 2);
                uint32_t rh[4], rl[4];
                ldmat4(rh, st + OFF_BH + brow * PITCHB + bcol);
                ldmat4(rl, st + OFF_BL + brow * PITCHB + bcol);
                bh[2 * nb][0] = rh[0]; bh[2 * nb][1] = rh[1];
                bh[2 * nb + 1][0] = rh[2]; bh[2 * nb + 1][1] = rh[3];
                bl[2 * nb][0] = rl[0]; bl[2 * nb][1] = rl[1];
                bl[2 * nb + 1][0] = rl[2]; bl[2 * nb + 1][1] = rl[3];
            }
            #pragma unroll
            for (int ma = 0; ma < 4; ma++)
                #pragma unroll
                for (int na = 0; na < 4; na++) {
                    mma16816(acc[ma][na], ah[ma], bh[na]);   // hi*hi
                    mma16816(acc[ma][na], ah[ma], bl[na]);   // hi*lo
                    mma16816(acc[ma][na], al[ma], bh[na]);   // lo*hi
                }
        }
        __syncthreads();   // protect stage before it is overwritten next round
    }

    // ---- epilogue ----
    #pragma unroll
    for (int ma = 0; ma < 4; ma++) {
        int gr = row0 + wm * 64 + ma * 16 + (lane >> 2);
        #pragma unroll
        for (int na = 0; na < 4; na++) {
            int gc = col0 + wn * 32 + na * 8 + (lane & 3) * 2;
            float2 v0, v1;
            v0.x = acc[ma][na][0] * alpha;
            v0.y = acc[ma][na][1] * alpha;
            v1.x = acc[ma][na][2] * alpha;
            v1.y = acc[ma][na][3] * alpha;
            *(float2*)(C + (size_t)gr * ldc + gc)       = v0;
            *(float2*)(C + (size_t)(gr + 8) * ldc + gc) = v1;
        }
    }
}

// ---------------- Elementwise split: x -> hi + lo (bf16) ----------------
__global__ void split_plain(const float* __restrict__ x, bf16* __restrict__ h,
                            bf16* __restrict__ l, int n)
{
    for (int i = blockIdx.x * blockDim.x + threadIdx.x; i < n; i += gridDim.x * blockDim.x) {
        float v = x[i];
        bf16 hi = __float2bfloat16(v);
        h[i] = hi;
        l[i] = __float2bfloat16(v - __bfloat162float(hi));
    }
}

// ---------------- Transpose + split: src[R,C] f32 -> dst[C,R] bf16 hi/lo ----------------
__global__ void split_transpose(const float* __restrict__ src, bf16* __restrict__ dh,
                                bf16* __restrict__ dl, int R, int C, long sS, long sD)
{
    __shared__ float t[32][33];
    src += (size_t)blockIdx.z * sS;
    dh  += (size_t)blockIdx.z * sD;
    dl  += (size_t)blockIdx.z * sD;
    int c0 = blockIdx.x * 32, r0 = blockIdx.y * 32;
    int tx = threadIdx.x, ty = threadIdx.y;     // (32, 8)
    #pragma unroll
    for (int i = 0; i < 4; i++)
        t[ty + i * 8][tx] = src[(size_t)(r0 + ty + i * 8) * C + c0 + tx];
    __syncthreads();
    #pragma unroll
    for (int i = 0; i < 4; i++) {
        float v = t[tx][ty + i * 8];
        size_t o = (size_t)(c0 + ty + i * 8) * R + r0 + tx;
        bf16 hi = __float2bfloat16(v);
        dh[o] = hi;
        dl[o] = __float2bfloat16(v - __bfloat162float(hi));
    }
}

// ---------------- Fused RMSNorm + RoPE -> split bf16 ----------------
__global__ void norm_rope_split(const float* __restrict__ x, const float* __restrict__ w,
                                const float* __restrict__ cosp, const float* __restrict__ sinp,
                                bf16* __restrict__ xh, bf16* __restrict__ xl, int nheads)
{
    int warp = (blockIdx.x * blockDim.x + threadIdx.x) >> 5;
    int lane = threadIdx.x & 31;
    if (warp >= BSn * nheads) return;
    int h  = warp % nheads;
    int bs = warp / nheads;
    int s  = bs & (Sn - 1);

    size_t base = (size_t)bs * nheads * DHn + (size_t)h * DHn;
    const float* row = x + base;
    float v0 = row[lane];
    float v1 = row[lane + 32];
    float v2 = row[lane + 64];
    float v3 = row[lane + 96];

    float ss = v0 * v0 + v1 * v1 + v2 * v2 + v3 * v3;
    #pragma unroll
    for (int o = 16; o > 0; o >>= 1) ss += __shfl_xor_sync(0xFFFFFFFFu, ss, o);
    float r = rsqrtf(ss * (1.0f / 128.0f) + 1e-6f);

    v0 = v0 * r * w[lane];
    v1 = v1 * r * w[lane + 32];
    v2 = v2 * r * w[lane + 64];
    v3 = v3 * r * w[lane + 96];

    const float* cs = cosp + (size_t)s * DHn;
    const float* sn = sinp + (size_t)s * DHn;
    float o0 = v0 * cs[lane]      - v2 * sn[lane];
    float o1 = v1 * cs[lane + 32] - v3 * sn[lane + 32];
    float o2 = v2 * cs[lane + 64] + v0 * sn[lane + 64];
    float o3 = v3 * cs[lane + 96] + v1 * sn[lane + 96];

    #pragma unroll
    for (int q = 0; q < 4; q++) {
        float ov = (q == 0) ? o0 : (q == 1) ? o1 : (q == 2) ? o2 : o3;
        size_t idx = base + lane + q * 32;
        bf16 hi = __float2bfloat16(ov);
        xh[idx] = hi;
        xl[idx] = __float2bfloat16(ov - __bfloat162float(hi));
    }
}

// ---------------- Causal-prefix softmax -> split bf16 probs ----------------
__global__ void softmax_split(const float* __restrict__ S, bf16* __restrict__ Ph,
                              bf16* __restrict__ Pl)
{
    __shared__ float red[8];
    size_t row = blockIdx.x;               // z*Sn + r
    int r = (int)(row & (Sn - 1));
    const float* p = S + row * (size_t)Sn;
    bf16* ph = Ph + row * (size_t)Sn;
    bf16* pl = Pl + row * (size_t)Sn;
    int tid = threadIdx.x, lane = tid & 31, wid = tid >> 5;
    int Kb = (r | 127) + 1;                // write bound (tile-rounded prefix)

    float v[8];
    float m = -INFINITY;
    #pragma unroll
    for (int i = 0; i < 8; i++) {
        int j = tid + i * 256;
        v[i] = (j <= r) ? p[j] : -INFINITY;
        m = fmaxf(m, v[i]);
    }
    #pragma unroll
    for (int o = 16; o > 0; o >>= 1) m = fmaxf(m, __shfl_xor_sync(0xFFFFFFFFu, m, o));
    if (lane == 0) red[wid] = m;
    __syncthreads();
    m = red[lane & 7];
    #pragma unroll
    for (int o = 4; o > 0; o >>= 1) m = fmaxf(m, __shfl_xor_sync(0xFFFFFFFFu, m, o));

    float s = 0.0f;
    #pragma unroll
    for (int i = 0; i < 8; i++) {
        v[i] = expf(v[i] - m);             // exp(-inf) = 0
        s += v[i];
    }
    #pragma unroll
    for (int o = 16; o > 0; o >>= 1) s += __shfl_xor_sync(0xFFFFFFFFu, s, o);
    if (lane == 0) red[wid] = s;
    __syncthreads();
    s = red[lane & 7];
    #pragma unroll
    for (int o = 4; o > 0; o >>= 1) s += __shfl_xor_sync(0xFFFFFFFFu, s, o);
    float inv = 1.0f / s;

    #pragma unroll
    for (int i = 0; i < 8; i++) {
        int j = tid + i * 256;
        if (j < Kb) {
            float pv = v[i] * inv;
            bf16 hi = __float2bfloat16(pv);
            ph[j] = hi;
            pl[j] = __float2bfloat16(pv - __bfloat162float(hi));
        }
    }
}

// ---------------- Launch ----------------
extern "C" void kernel_launch(void* const* d_in, const int* in_sizes, int n_in,
                              void* d_out, int out_size)
{
    (void)in_sizes; (void)n_in; (void)out_size;
    const float* X    = (const float*)d_in[0];
    const float* cosp = (const float*)d_in[2];
    const float* sinp = (const float*)d_in[3];
    const float* Wq   = (const float*)d_in[4];
    const float* Wk   = (const float*)d_in[5];
    const float* Wv   = (const float*)d_in[6];
    const float* Wo   = (const float*)d_in[7];
    const float* qw   = (const float*)d_in[8];
    const float* kw   = (const float*)d_in[9];
    float* out = (float*)d_out;

    cudaFuncSetAttribute(gemm_split, cudaFuncAttributeMaxDynamicSharedMemorySize, SMEM_BYTES);

    void *p;
    #define SYM(v, s) cudaGetSymbolAddress(&p, s); auto v = (decltype(&s[0]))p;
    SYM(Q,  g_Q)   SYM(Kf, g_K)   SYM(Vf, g_V)   SYM(Sc, g_S)   SYM(Af, g_A)
    SYM(Xh, g_Xh)  SYM(Xl, g_Xl)
    SYM(Wqh, g_Wqh) SYM(Wql, g_Wql) SYM(Wkh, g_Wkh) SYM(Wkl, g_Wkl)
    SYM(Wvh, g_Wvh) SYM(Wvl, g_Wvl) SYM(Woh, g_Woh) SYM(Wol, g_Wol)
    SYM(Qh, g_Qh)  SYM(Ql, g_Ql)  SYM(Kh, g_Kh)  SYM(Kl, g_Kl)
    SYM(Vth, g_Vth) SYM(Vtl, g_Vtl)
    SYM(Ph, g_Ph)  SYM(Pl, g_Pl)  SYM(Ah, g_Ah)  SYM(Al, g_Al)
    #undef SYM

    const float scale = 0.08838834764831845f;   // 1/sqrt(128)

    // 0) Splits of inputs (X plain; weights transposed to [N,K] K-major)
    split_plain<<<2048, 256>>>(X, Xh, Xl, BSn * HIDn);
    split_transpose<<<dim3(QDIM / 32, HIDn / 32, 1), dim3(32, 8)>>>(Wq, Wqh, Wql, HIDn, QDIM, 0, 0);
    split_transpose<<<dim3(KVDIM / 32, HIDn / 32, 1), dim3(32, 8)>>>(Wk, Wkh, Wkl, HIDn, KVDIM, 0, 0);
    split_transpose<<<dim3(KVDIM / 32, HIDn / 32, 1), dim3(32, 8)>>>(Wv, Wvh, Wvl, HIDn, KVDIM, 0, 0);
    split_transpose<<<dim3(HIDn / 32, QDIM / 32, 1), dim3(32, 8)>>>(Wo, Woh, Wol, QDIM, HIDn, 0, 0);

    // 1) Projections (fp32 outputs)
    gemm_split<<<dim3(QDIM / 128, BSn / 128, 1), 256, SMEM_BYTES>>>(
        Xh, Xl, Wqh, Wql, Q, HIDn, HIDn, QDIM, HIDn, 0, 1.0f);
    gemm_split<<<dim3(KVDIM / 128, BSn / 128, 1), 256, SMEM_BYTES>>>(
        Xh, Xl, Wkh, Wkl, Kf, HIDn, HIDn, KVDIM, HIDn, 0, 1.0f);
    gemm_split<<<dim3(KVDIM / 128, BSn / 128, 1), 256, SMEM_BYTES>>>(
        Xh, Xl, Wvh, Wvl, Vf, HIDn, HIDn, KVDIM, HIDn, 0, 1.0f);

    // 2) RMSNorm + RoPE -> split bf16 Q/K;   V -> transposed split [b][kv*dh][s]
    norm_rope_split<<<(BSn * NHn) / 8, 256>>>(Q, qw, cosp, sinp, Qh, Ql, NHn);
    norm_rope_split<<<(BSn * NKVn) / 8, 256>>>(Kf, kw, cosp, sinp, Kh, Kl, NKVn);
    split_transpose<<<dim3(KVDIM / 32, Sn / 32, Bn), dim3(32, 8)>>>(
        Vf, Vth, Vtl, Sn, KVDIM, (long)Sn * KVDIM, (long)KVDIM * Sn);

    // 3) Scores = scale * Q @ K^T   (causal upper tiles skipped entirely)
    gemm_split<<<dim3(Sn / 128, Sn / 128, Bn * NHn), 256, SMEM_BYTES>>>(
        Qh, Ql, Kh, Kl, Sc, QDIM, KVDIM, Sn, DHn, 1, scale);

    // 4) Prefix softmax -> bf16 split probs
    softmax_split<<<Bn * NHn * Sn, 256>>>(Sc, Ph, Pl);

    // 5) attn = P @ V   (K clipped to causal prefix per row-tile)
    gemm_split<<<dim3(1, Sn / 128, Bn * NHn), 256, SMEM_BYTES>>>(
        Ph, Pl, Vth, Vtl, Af, Sn, Sn, QDIM, Sn, 2, 1.0f);

    // 6) Output projection
    split_plain<<<2048, 256>>>(Af, Ah, Al, BSn * QDIM);
    gemm_split<<<dim3(HIDn / 128, BSn / 128, 1), 256, SMEM_BYTES>>>(
        Ah, Al, Woh, Wol, out, QDIM, QDIM, HIDn, QDIM, 0, 1.0f);
}

// round 4
// speedup vs baseline: 3.4534x; 1.2034x over previous
#include <cuda_runtime.h>
#include <cuda_bf16.h>
#include <math.h>
#include <stdint.h>

// ---------------- Problem constants ----------------
#define Bn   2
#define Sn   2048
#define HIDn 2048
#define NHn  16
#define NKVn 4
#define DHn  128
#define BSn  (Bn * Sn)           // 4096
#define QDIM (NHn * DHn)         // 2048
#define KVDIM (NKVn * DHn)       // 512
#define SCALE 0.08838834764831845f

typedef __nv_bfloat16 bf16;

// ---------------- PTX helpers (base ISA, sm_80+) ----------------
__device__ __forceinline__ uint32_t smem_u32(const void* p) {
    uint32_t a;
    asm("{ .reg .u64 t; cvta.to.shared.u64 t, %1; cvt.u32.u64 %0, t; }" : "=r"(a) : "l"(p));
    return a;
}
__device__ __forceinline__ void cp_async16(uint32_t saddr, const void* gaddr) {
    asm volatile("cp.async.cg.shared.global [%0], [%1], 16;" :: "r"(saddr), "l"(gaddr));
}
__device__ __forceinline__ void cp_commit() {
    asm volatile("cp.async.commit_group;" ::: "memory");
}
template <int N>
__device__ __forceinline__ void cp_wait() {
    asm volatile("cp.async.wait_group %0;" :: "n"(N) : "memory");
}
__device__ __forceinline__ void ldmat4(uint32_t* r, uint32_t addr) {
    asm volatile("ldmatrix.sync.aligned.m8n8.x4.shared.b16 {%0,%1,%2,%3}, [%4];"
                 : "=r"(r[0]), "=r"(r[1]), "=r"(r[2]), "=r"(r[3]) : "r"(addr));
}
__device__ __forceinline__ void mma16816(float* c, const uint32_t* a, const uint32_t* b) {
    asm volatile("mma.sync.aligned.m16n8k16.row.col.f32.bf16.bf16.f32 "
                 "{%0,%1,%2,%3}, {%4,%5,%6,%7}, {%8,%9}, {%0,%1,%2,%3};"
                 : "+f"(c[0]), "+f"(c[1]), "+f"(c[2]), "+f"(c[3])
                 : "r"(a[0]), "r"(a[1]), "r"(a[2]), "r"(a[3]), "r"(b[0]), "r"(b[1]));
}
__device__ __forceinline__ uint32_t pack_bf16(float x, float y) {
    __nv_bfloat162 t;
    t.x = __float2bfloat16(x);
    t.y = __float2bfloat16(y);
    return *(uint32_t*)&t;
}
__device__ __forceinline__ uint32_t pack_bf16_lo(float x, float y, uint32_t hi) {
    __nv_bfloat162 h = *(__nv_bfloat162*)&hi;
    return pack_bf16(x - __bfloat162float(h.x), y - __bfloat162float(h.y));
}

// ---------------- Scratch (device globals) ----------------
__device__ __align__(256) float g_Q[(size_t)BSn * QDIM];
__device__ __align__(256) float g_K[(size_t)BSn * KVDIM];
__device__ __align__(256) float g_V[(size_t)BSn * KVDIM];

__device__ __align__(256) bf16 g_Xh[(size_t)BSn * HIDn];
__device__ __align__(256) bf16 g_Xl[(size_t)BSn * HIDn];
__device__ __align__(256) bf16 g_Wqh[(size_t)QDIM * HIDn];
__device__ __align__(256) bf16 g_Wql[(size_t)QDIM * HIDn];
__device__ __align__(256) bf16 g_Wkh[(size_t)KVDIM * HIDn];
__device__ __align__(256) bf16 g_Wkl[(size_t)KVDIM * HIDn];
__device__ __align__(256) bf16 g_Wvh[(size_t)KVDIM * HIDn];
__device__ __align__(256) bf16 g_Wvl[(size_t)KVDIM * HIDn];
__device__ __align__(256) bf16 g_Woh[(size_t)HIDn * QDIM];
__device__ __align__(256) bf16 g_Wol[(size_t)HIDn * QDIM];
__device__ __align__(256) bf16 g_Qh[(size_t)BSn * QDIM];
__device__ __align__(256) bf16 g_Ql[(size_t)BSn * QDIM];
__device__ __align__(256) bf16 g_Kh[(size_t)BSn * KVDIM];
__device__ __align__(256) bf16 g_Kl[(size_t)BSn * KVDIM];
__device__ __align__(256) bf16 g_Vth[(size_t)Bn * KVDIM * Sn];
__device__ __align__(256) bf16 g_Vtl[(size_t)Bn * KVDIM * Sn];
__device__ __align__(256) bf16 g_Ah[(size_t)BSn * QDIM];
__device__ __align__(256) bf16 g_Al[(size_t)BSn * QDIM];

// ================= Split-bf16 mma.sync GEMM (projections) =================
// C[M,N] = (Ah+Al)[M,K] @ (Bh+Bl)[N,K]^T   (both K-major), 3-stage cp.async.
#define PITCHB   80
#define TILE_B   (128 * PITCHB)
#define OFF_AH   0
#define OFF_AL   (TILE_B)
#define OFF_BH   (2 * TILE_B)
#define OFF_BL   (3 * TILE_B)
#define STAGE_B  (4 * TILE_B)          // 40960
#define GSMEM_BYTES (3 * STAGE_B)      // 122880

__global__ void __launch_bounds__(256, 1)
gemm_split(const bf16* __restrict__ Ah, const bf16* __restrict__ Al,
           const bf16* __restrict__ Bh, const bf16* __restrict__ Bl,
           float* __restrict__ C,
           int lda, int ldb, int ldc, int K)
{
    extern __shared__ __align__(128) char smem[];
    const int row0 = blockIdx.y * 128;
    const int col0 = blockIdx.x * 128;

    const int tid  = threadIdx.x;
    const int lane = tid & 31;
    const int warp = tid >> 5;
    const int wm   = warp >> 2;
    const int wn   = warp & 3;

    float acc[4][4][4];
    #pragma unroll
    for (int i = 0; i < 4; i++)
        #pragma unroll
        for (int j = 0; j < 4; j++)
            #pragma unroll
            for (int q = 0; q < 4; q++)
                acc[i][j][q] = 0.0f;

    const uint32_t sbase = smem_u32(smem);
    const int nch = K >> 5;

    auto load_stage = [&](int st_idx, int k0) {
        char* st = smem + st_idx * STAGE_B;
        #pragma unroll
        for (int ii = 0; ii < 2; ii++) {
            int i = tid + ii * 256;
            int r = i >> 2, c = i & 3;
            uint32_t dof = (uint32_t)(r * PITCHB + c * 16);
            size_t ga = (size_t)(row0 + r) * lda + k0 + c * 8;
            size_t gb = (size_t)(col0 + r) * ldb + k0 + c * 8;
            cp_async16(smem_u32(st + OFF_AH + dof), Ah + ga);
            cp_async16(smem_u32(st + OFF_AL + dof), Al + ga);
            cp_async16(smem_u32(st + OFF_BH + dof), Bh + gb);
            cp_async16(smem_u32(st + OFF_BL + dof), Bl + gb);
        }
        cp_commit();
    };

    load_stage(0, 0);
    if (nch > 1) load_stage(1, 32);

    int sidx = 0;
    for (int ch = 0; ch < nch; ch++) {
        if (ch + 2 < nch) {
            load_stage((sidx + 2) % 3, (ch + 2) << 5);
            cp_wait<2>();
        } else if (ch + 1 < nch) {
            cp_wait<1>();
        } else {
            cp_wait<0>();
        }
        __syncthreads();

        const uint32_t st = sbase + (uint32_t)(sidx * STAGE_B);

        #pragma unroll
        for (int kk = 0; kk < 32; kk += 16) {
            uint32_t ah[4][4], al[4][4];
            #pragma unroll
            for (int ma = 0; ma < 4; ma++) {
                uint32_t arow = (uint32_t)(wm * 64 + ma * 16 + (lane & 15));
                uint32_t acol = (uint32_t)((kk + ((lane >> 4) << 3)) * 2);
                ldmat4(ah[ma], st + OFF_AH + arow * PITCHB + acol);
                ldmat4(al[ma], st + OFF_AL + arow * PITCHB + acol);
            }
            uint32_t bh[4][2], bl[4][2];
            #pragma unroll
            for (int nb = 0; nb < 2; nb++) {
                uint32_t brow = (uint32_t)(wn * 32 + nb * 16 + ((lane >> 4) << 3) + (lane & 7));
                uint32_t bcol = (uint32_t)((kk + (((lane >> 3) & 1) << 3)) * 2);
                uint32_t rh[4], rl[4];
                ldmat4(rh, st + OFF_BH + brow * PITCHB + bcol);
                ldmat4(rl, st + OFF_BL + brow * PITCHB + bcol);
                bh[2 * nb][0] = rh[0]; bh[2 * nb][1] = rh[1];
                bh[2 * nb + 1][0] = rh[2]; bh[2 * nb + 1][1] = rh[3];
                bl[2 * nb][0] = rl[0]; bl[2 * nb][1] = rl[1];
                bl[2 * nb + 1][0] = rl[2]; bl[2 * nb + 1][1] = rl[3];
            }
            #pragma unroll
            for (int ma = 0; ma < 4; ma++)
                #pragma unroll
                for (int na = 0; na < 4; na++) {
                    mma16816(acc[ma][na], ah[ma], bh[na]);
                    mma16816(acc[ma][na], ah[ma], bl[na]);
                    mma16816(acc[ma][na], al[ma], bh[na]);
                }
        }
        __syncthreads();
        sidx = (sidx + 1) % 3;
    }

    #pragma unroll
    for (int ma = 0; ma < 4; ma++) {
        int gr = row0 + wm * 64 + ma * 16 + (lane >> 2);
        #pragma unroll
        for (int na = 0; na < 4; na++) {
            int gc = col0 + wn * 32 + na * 8 + (lane & 3) * 2;
            float2 v0, v1;
            v0.x = acc[ma][na][0];
            v0.y = acc[ma][na][1];
            v1.x = acc[ma][na][2];
            v1.y = acc[ma][na][3];
            *(float2*)(C + (size_t)gr * ldc + gc)       = v0;
            *(float2*)(C + (size_t)(gr + 8) * ldc + gc) = v1;
        }
    }
}

// ================= Fused flash attention =================
// Per CTA: (b, h, row-tile i of 128 q rows). Iterates key tiles j=0..i.
// S = 3-pass split-bf16 mma; online softmax in regs; P repacked in-register
// to A-frags; P@V = 3-pass split mma; writes split-bf16 attention output.
#define FPITCH 272
#define FT     (128 * FPITCH)          // 34816
#define FOFF_QH 0
#define FOFF_QL (FT)
#define FOFF_KH (2 * FT)
#define FOFF_KL (3 * FT)
#define FOFF_VH (4 * FT)
#define FOFF_VL (5 * FT)
#define FSMEM_BYTES (6 * FT)           // 208896

__global__ void __launch_bounds__(256, 1)
flash_kernel(const bf16* __restrict__ Qh, const bf16* __restrict__ Ql,
             const bf16* __restrict__ Kh, const bf16* __restrict__ Kl,
             const bf16* __restrict__ Vh, const bf16* __restrict__ Vl,
             bf16* __restrict__ Ah, bf16* __restrict__ Al)
{
    extern __shared__ __align__(128) char smem[];
    const int i    = 15 - blockIdx.x;      // row tile (heavy first)
    const int bh   = blockIdx.y;
    const int b    = bh >> 4, h = bh & 15, kv = h >> 2;
    const int row0 = i * 128;
    const int bSn  = b * Sn;
    const int kvoff = kv * DHn;
    const size_t vbase = (size_t)b * KVDIM * Sn;

    const int tid  = threadIdx.x;
    const int lane = tid & 31;
    const int warp = tid >> 5;
    const int w16  = warp * 16;

    const uint32_t sb = smem_u32(smem);
    const uint32_t sQh = sb + FOFF_QH, sQl = sb + FOFF_QL;
    const uint32_t sKh = sb + FOFF_KH, sKl = sb + FOFF_KL;
    const uint32_t sVh = sb + FOFF_VH, sVl = sb + FOFF_VL;

    auto ldQ = [&]() {
        #pragma unroll
        for (int ii = 0; ii < 8; ii++) {
            int id = tid + ii * 256;
            int r = id >> 4, c = id & 15;
            uint32_t so = (uint32_t)(r * FPITCH + c * 16);
            size_t g = (size_t)(bSn + row0 + r) * QDIM + h * DHn + c * 8;
            cp_async16(sQh + so, Qh + g);
            cp_async16(sQl + so, Ql + g);
        }
    };
    auto ldK = [&](int j0) {
        #pragma unroll
        for (int ii = 0; ii < 8; ii++) {
            int id = tid + ii * 256;
            int r = id >> 4, c = id & 15;
            uint32_t so = (uint32_t)(r * FPITCH + c * 16);
            size_t g = (size_t)(bSn + j0 + r) * KVDIM + kvoff + c * 8;
            cp_async16(sKh + so, Kh + g);
            cp_async16(sKl + so, Kl + g);
        }
    };
    auto ldV = [&](int j0) {
        #pragma unroll
        for (int ii = 0; ii < 8; ii++) {
            int id = tid + ii * 256;
            int r = id >> 4, c = id & 15;
            uint32_t so = (uint32_t)(r * FPITCH + c * 16);
            size_t g = vbase + (size_t)(kvoff + r) * Sn + j0 + c * 8;
            cp_async16(sVh + so, Vh + g);
            cp_async16(sVl + so, Vl + g);
        }
    };

    float o[16][4];
    #pragma unroll
    for (int nt = 0; nt < 16; nt++)
        #pragma unroll
        for (int q = 0; q < 4; q++) o[nt][q] = 0.0f;
    float m0 = -INFINITY, m1 = -INFINITY, l0 = 0.0f, l1 = 0.0f;

    ldQ();
    ldK(0);
    cp_commit();                       // group: Q + K0

    for (int j = 0; j <= i; j++) {
        const int j0 = j << 7;
        ldV(j0);
        cp_commit();                   // group: V_j
        cp_wait<1>();                  // K_j (and Q) ready; V_j may pend
        __syncthreads();

        // ---- S = Q @ K^T (3-pass split) ----
        float s[16][4];
        #pragma unroll
        for (int nt = 0; nt < 16; nt++)
            #pragma unroll
            for (int q = 0; q < 4; q++) s[nt][q] = 0.0f;

        #pragma unroll
        for (int kk = 0; kk < 8; kk++) {
            uint32_t aH[4], aL[4];
            uint32_t aoff = (uint32_t)((w16 + (lane & 15)) * FPITCH +
                                       (kk * 16 + ((lane >> 4) << 3)) * 2);
            ldmat4(aH, sQh + aoff);
            ldmat4(aL, sQl + aoff);
            #pragma unroll
            for (int np = 0; np < 8; np++) {
                uint32_t brow = (uint32_t)(np * 16 + ((lane >> 4) << 3) + (lane & 7));
                uint32_t boff = brow * FPITCH +
                                (uint32_t)((kk * 16 + (((lane >> 3) & 1) << 3)) * 2);
                uint32_t rh[4], rl[4];
                ldmat4(rh, sKh + boff);
                ldmat4(rl, sKl + boff);
                uint32_t b0h[2] = {rh[0], rh[1]}, b1h[2] = {rh[2], rh[3]};
                uint32_t b0l[2] = {rl[0], rl[1]}, b1l[2] = {rl[2], rl[3]};
                mma16816(s[2 * np],     aH, b0h);
                mma16816(s[2 * np],     aH, b0l);
                mma16816(s[2 * np],     aL, b0h);
                mma16816(s[2 * np + 1], aH, b1h);
                mma16816(s[2 * np + 1], aH, b1l);
                mma16816(s[2 * np + 1], aL, b1h);
            }
        }

        __syncthreads();               // all warps done reading K smem
        if (j < i) ldK(j0 + 128);
        cp_commit();                   // group: K_{j+1} (possibly empty)

        // ---- online softmax ----
        const int grow0 = row0 + w16 + (lane >> 2);
        const bool diag = (j == i);
        float nm0 = -INFINITY, nm1 = -INFINITY;
        #pragma unroll
        for (int nt = 0; nt < 16; nt++) {
            #pragma unroll
            for (int q = 0; q < 4; q++) {
                float v = s[nt][q] * SCALE;
                if (diag) {
                    int col = j0 + nt * 8 + (lane & 3) * 2 + (q & 1);
                    int gr = (q < 2) ? grow0 : grow0 + 8;
                    if (col > gr) v = -INFINITY;
                }
                s[nt][q] = v;
            }
            nm0 = fmaxf(nm0, fmaxf(s[nt][0], s[nt][1]));
            nm1 = fmaxf(nm1, fmaxf(s[nt][2], s[nt][3]));
        }
        nm0 = fmaxf(nm0, __shfl_xor_sync(0xFFFFFFFFu, nm0, 1));
        nm0 = fmaxf(nm0, __shfl_xor_sync(0xFFFFFFFFu, nm0, 2));
        nm1 = fmaxf(nm1, __shfl_xor_sync(0xFFFFFFFFu, nm1, 1));
        nm1 = fmaxf(nm1, __shfl_xor_sync(0xFFFFFFFFu, nm1, 2));

        float mn0 = fmaxf(m0, nm0), mn1 = fmaxf(m1, nm1);
        float f0 = (m0 > -1e30f) ? __expf(m0 - mn0) : 0.0f;
        float f1 = (m1 > -1e30f) ? __expf(m1 - mn1) : 0.0f;
        m0 = mn0; m1 = mn1;

        float rs0 = 0.0f, rs1 = 0.0f;
        #pragma unroll
        for (int nt = 0; nt < 16; nt++) {
            float p0 = __expf(s[nt][0] - mn0);
            float p1 = __expf(s[nt][1] - mn0);
            float p2 = __expf(s[nt][2] - mn1);
            float p3 = __expf(s[nt][3] - mn1);
            s[nt][0] = p0; s[nt][1] = p1; s[nt][2] = p2; s[nt][3] = p3;
            rs0 += p0 + p1;
            rs1 += p2 + p3;
        }
        rs0 += __shfl_xor_sync(0xFFFFFFFFu, rs0, 1);
        rs0 += __shfl_xor_sync(0xFFFFFFFFu, rs0, 2);
        rs1 += __shfl_xor_sync(0xFFFFFFFFu, rs1, 1);
        rs1 += __shfl_xor_sync(0xFFFFFFFFu, rs1, 2);
        l0 = l0 * f0 + rs0;
        l1 = l1 * f1 + rs1;
        #pragma unroll
        for (int nt = 0; nt < 16; nt++) {
            o[nt][0] *= f0; o[nt][1] *= f0;
            o[nt][2] *= f1; o[nt][3] *= f1;
        }

        cp_wait<1>();                  // V_j ready; K_{j+1} may pend
        __syncthreads();

        // ---- O += P @ V (3-pass split; P frags built in-register) ----
        #pragma unroll
        for (int kk = 0; kk < 8; kk++) {
            uint32_t pH[4], pL[4];
            pH[0] = pack_bf16(s[2 * kk][0],     s[2 * kk][1]);
            pH[1] = pack_bf16(s[2 * kk][2],     s[2 * kk][3]);
            pH[2] = pack_bf16(s[2 * kk + 1][0], s[2 * kk + 1][1]);
            pH[3] = pack_bf16(s[2 * kk + 1][2], s[2 * kk + 1][3]);
            pL[0] = pack_bf16_lo(s[2 * kk][0],     s[2 * kk][1],     pH[0]);
            pL[1] = pack_bf16_lo(s[2 * kk][2],     s[2 * kk][3],     pH[1]);
            pL[2] = pack_bf16_lo(s[2 * kk + 1][0], s[2 * kk + 1][1], pH[2]);
            pL[3] = pack_bf16_lo(s[2 * kk + 1][2], s[2 * kk + 1][3], pH[3]);
            #pragma unroll
            for (int np = 0; np < 8; np++) {
                uint32_t brow = (uint32_t)(np * 16 + ((lane >> 4) << 3) + (lane & 7));
                uint32_t boff = brow * FPITCH +
                                (uint32_t)((kk * 16 + (((lane >> 3) & 1) << 3)) * 2);
                uint32_t rh[4], rl[4];
                ldmat4(rh, sVh + boff);
                ldmat4(rl, sVl + boff);
                uint32_t b0h[2] = {rh[0], rh[1]}, b1h[2] = {rh[2], rh[3]};
                uint32_t b0l[2] = {rl[0], rl[1]}, b1l[2] = {rl[2], rl[3]};
                mma16816(o[2 * np],     pH, b0h);
                mma16816(o[2 * np],     pL, b0h);
                mma16816(o[2 * np],     pH, b0l);
                mma16816(o[2 * np + 1], pH, b1h);
                mma16816(o[2 * np + 1], pL, b1h);
                mma16816(o[2 * np + 1], pH, b1l);
            }
        }
        __syncthreads();               // all warps done reading V smem
    }

    // ---- epilogue: out = O / l, split into bf16 hi/lo ----
    const float inv0 = 1.0f / l0, inv1 = 1.0f / l1;
    const int gr0 = bSn + row0 + w16 + (lane >> 2);
    const size_t cbase = (size_t)h * DHn + (lane & 3) * 2;
    #pragma unroll
    for (int nt = 0; nt < 16; nt++) {
        size_t i0 = (size_t)gr0 * QDIM + cbase + nt * 8;
        size_t i1 = (size_t)(gr0 + 8) * QDIM + cbase + nt * 8;
        float v0 = o[nt][0] * inv0, v1 = o[nt][1] * inv0;
        float v2 = o[nt][2] * inv1, v3 = o[nt][3] * inv1;
        uint32_t h0 = pack_bf16(v0, v1);
        uint32_t h1 = pack_bf16(v2, v3);
        *(uint32_t*)(Ah + i0) = h0;
        *(uint32_t*)(Ah + i1) = h1;
        *(uint32_t*)(Al + i0) = pack_bf16_lo(v0, v1, h0);
        *(uint32_t*)(Al + i1) = pack_bf16_lo(v2, v3, h1);
    }
}

// ---------------- Elementwise split ----------------
__global__ void split_plain(const float* __restrict__ x, bf16* __restrict__ h,
                            bf16* __restrict__ l, int n)
{
    for (int i = blockIdx.x * blockDim.x + threadIdx.x; i < n; i += gridDim.x * blockDim.x) {
        float v = x[i];
        bf16 hi = __float2bfloat16(v);
        h[i] = hi;
        l[i] = __float2bfloat16(v - __bfloat162float(hi));
    }
}

// ---------------- Transpose + split ----------------
__global__ void split_transpose(const float* __restrict__ src, bf16* __restrict__ dh,
                                bf16* __restrict__ dl, int R, int C, long sS, long sD)
{
    __shared__ float t[32][33];
    src += (size_t)blockIdx.z * sS;
    dh  += (size_t)blockIdx.z * sD;
    dl  += (size_t)blockIdx.z * sD;
    int c0 = blockIdx.x * 32, r0 = blockIdx.y * 32;
    int tx = threadIdx.x, ty = threadIdx.y;
    #pragma unroll
    for (int i = 0; i < 4; i++)
        t[ty + i * 8][tx] = src[(size_t)(r0 + ty + i * 8) * C + c0 + tx];
    __syncthreads();
    #pragma unroll
    for (int i = 0; i < 4; i++) {
        float v = t[tx][ty + i * 8];
        size_t o = (size_t)(c0 + ty + i * 8) * R + r0 + tx;
        bf16 hi = __float2bfloat16(v);
        dh[o] = hi;
        dl[o] = __float2bfloat16(v - __bfloat162float(hi));
    }
}

// ---------------- Fused RMSNorm + RoPE -> split bf16 ----------------
__global__ void norm_rope_split(const float* __restrict__ x, const float* __restrict__ w,
                                const float* __restrict__ cosp, const float* __restrict__ sinp,
                                bf16* __restrict__ xh, bf16* __restrict__ xl, int nheads)
{
    int warp = (blockIdx.x * blockDim.x + threadIdx.x) >> 5;
    int lane = threadIdx.x & 31;
    if (warp >= BSn * nheads) return;
    int h  = warp % nheads;
    int bs = warp / nheads;
    int s  = bs & (Sn - 1);

    size_t base = (size_t)bs * nheads * DHn + (size_t)h * DHn;
    const float* row = x + base;
    float v0 = row[lane];
    float v1 = row[lane + 32];
    float v2 = row[lane + 64];
    float v3 = row[lane + 96];

    float ss = v0 * v0 + v1 * v1 + v2 * v2 + v3 * v3;
    #pragma unroll
    for (int o = 16; o > 0; o >>= 1) ss += __shfl_xor_sync(0xFFFFFFFFu, ss, o);
    float r = rsqrtf(ss * (1.0f / 128.0f) + 1e-6f);

    v0 = v0 * r * w[lane];
    v1 = v1 * r * w[lane + 32];
    v2 = v2 * r * w[lane + 64];
    v3 = v3 * r * w[lane + 96];

    const float* cs = cosp + (size_t)s * DHn;
    const float* sn = sinp + (size_t)s * DHn;
    float o0 = v0 * cs[lane]      - v2 * sn[lane];
    float o1 = v1 * cs[lane + 32] - v3 * sn[lane + 32];
    float o2 = v2 * cs[lane + 64] + v0 * sn[lane + 64];
    float o3 = v3 * cs[lane + 96] + v1 * sn[lane + 96];

    #pragma unroll
    for (int q = 0; q < 4; q++) {
        float ov = (q == 0) ? o0 : (q == 1) ? o1 : (q == 2) ? o2 : o3;
        size_t idx = base + lane + q * 32;
        bf16 hi = __float2bfloat16(ov);
        xh[idx] = hi;
        xl[idx] = __float2bfloat16(ov - __bfloat162float(hi));
    }
}

// ---------------- Launch ----------------
extern "C" void kernel_launch(void* const* d_in, const int* in_sizes, int n_in,
                              void* d_out, int out_size)
{
    (void)in_sizes; (void)n_in; (void)out_size;
    const float* X    = (const float*)d_in[0];
    const float* cosp = (const float*)d_in[2];
    const float* sinp = (const float*)d_in[3];
    const float* Wq   = (const float*)d_in[4];
    const float* Wk   = (const float*)d_in[5];
    const float* Wv   = (const float*)d_in[6];
    const float* Wo   = (const float*)d_in[7];
    const float* qw   = (const float*)d_in[8];
    const float* kw   = (const float*)d_in[9];
    float* out = (float*)d_out;

    cudaFuncSetAttribute(gemm_split, cudaFuncAttributeMaxDynamicSharedMemorySize, GSMEM_BYTES);
    cudaFuncSetAttribute(flash_kernel, cudaFuncAttributeMaxDynamicSharedMemorySize, FSMEM_BYTES);

    void *p;
    #define SYM(v, s) cudaGetSymbolAddress(&p, s); auto v = (decltype(&s[0]))p;
    SYM(Q,  g_Q)   SYM(Kf, g_K)   SYM(Vf, g_V)
    SYM(Xh, g_Xh)  SYM(Xl, g_Xl)
    SYM(Wqh, g_Wqh) SYM(Wql, g_Wql) SYM(Wkh, g_Wkh) SYM(Wkl, g_Wkl)
    SYM(Wvh, g_Wvh) SYM(Wvl, g_Wvl) SYM(Woh, g_Woh) SYM(Wol, g_Wol)
    SYM(Qh, g_Qh)  SYM(Ql, g_Ql)  SYM(Kh, g_Kh)  SYM(Kl, g_Kl)
    SYM(Vth, g_Vth) SYM(Vtl, g_Vtl)
    SYM(Ah, g_Ah)  SYM(Al, g_Al)
    #undef SYM

    // 0) Splits of inputs
    split_plain<<<2048, 256>>>(X, Xh, Xl, BSn * HIDn);
    split_transpose<<<dim3(QDIM / 32, HIDn / 32, 1), dim3(32, 8)>>>(Wq, Wqh, Wql, HIDn, QDIM, 0, 0);
    split_transpose<<<dim3(KVDIM / 32, HIDn / 32, 1), dim3(32, 8)>>>(Wk, Wkh, Wkl, HIDn, KVDIM, 0, 0);
    split_transpose<<<dim3(KVDIM / 32, HIDn / 32, 1), dim3(32, 8)>>>(Wv, Wvh, Wvl, HIDn, KVDIM, 0, 0);
    split_transpose<<<dim3(HIDn / 32, QDIM / 32, 1), dim3(32, 8)>>>(Wo, Woh, Wol, QDIM, HIDn, 0, 0);

    // 1) Projections
    gemm_split<<<dim3(QDIM / 128, BSn / 128), 256, GSMEM_BYTES>>>(
        Xh, Xl, Wqh, Wql, Q, HIDn, HIDn, QDIM, HIDn);
    gemm_split<<<dim3(KVDIM / 128, BSn / 128), 256, GSMEM_BYTES>>>(
        Xh, Xl, Wkh, Wkl, Kf, HIDn, HIDn, KVDIM, HIDn);
    gemm_split<<<dim3(KVDIM / 128, BSn / 128), 256, GSMEM_BYTES>>>(
        Xh, Xl, Wvh, Wvl, Vf, HIDn, HIDn, KVDIM, HIDn);

    // 2) RMSNorm+RoPE -> split Q/K;  V -> transposed split [b][kv*dh][s]
    norm_rope_split<<<(BSn * NHn) / 8, 256>>>(Q, qw, cosp, sinp, Qh, Ql, NHn);
    norm_rope_split<<<(BSn * NKVn) / 8, 256>>>(Kf, kw, cosp, sinp, Kh, Kl, NKVn);
    split_transpose<<<dim3(KVDIM / 32, Sn / 32, Bn), dim3(32, 8)>>>(
        Vf, Vth, Vtl, Sn, KVDIM, (long)Sn * KVDIM, (long)KVDIM * Sn);

    // 3) Fused flash attention -> split bf16 output
    flash_kernel<<<dim3(Sn / 128, Bn * NHn), 256, FSMEM_BYTES>>>(
        Qh, Ql, Kh, Kl, Vth, Vtl, Ah, Al);

    // 4) Output projection
    gemm_split<<<dim3(HIDn / 128, BSn / 128), 256, GSMEM_BYTES>>>(
        Ah, Al, Woh, Wol, out, QDIM, QDIM, HIDn, QDIM);
}

// round 5
// speedup vs baseline: 4.7513x; 1.3759x over previous
#include <cuda_runtime.h>
#include <cuda_fp16.h>
#include <math.h>
#include <stdint.h>

// ---------------- Problem constants ----------------
#define Bn   2
#define Sn   2048
#define HIDn 2048
#define NHn  16
#define NKVn 4
#define DHn  128
#define BSn  (Bn * Sn)           // 4096
#define QDIM (NHn * DHn)         // 2048
#define KVDIM (NKVn * DHn)       // 512
#define SCALE 0.08838834764831845f

typedef __half fp16;

// ---------------- PTX helpers (base ISA, sm_80+) ----------------
__device__ __forceinline__ uint32_t smem_u32(const void* p) {
    uint32_t a;
    asm("{ .reg .u64 t; cvta.to.shared.u64 t, %1; cvt.u32.u64 %0, t; }" : "=r"(a) : "l"(p));
    return a;
}
__device__ __forceinline__ void cp_async16(uint32_t saddr, const void* gaddr) {
    asm volatile("cp.async.cg.shared.global [%0], [%1], 16;" :: "r"(saddr), "l"(gaddr));
}
__device__ __forceinline__ void cp_commit() {
    asm volatile("cp.async.commit_group;" ::: "memory");
}
template <int N>
__device__ __forceinline__ void cp_wait() {
    asm volatile("cp.async.wait_group %0;" :: "n"(N) : "memory");
}
__device__ __forceinline__ void ldmat4(uint32_t* r, uint32_t addr) {
    asm volatile("ldmatrix.sync.aligned.m8n8.x4.shared.b16 {%0,%1,%2,%3}, [%4];"
                 : "=r"(r[0]), "=r"(r[1]), "=r"(r[2]), "=r"(r[3]) : "r"(addr));
}
__device__ __forceinline__ void mma16816(float* c, const uint32_t* a, const uint32_t* b) {
    asm volatile("mma.sync.aligned.m16n8k16.row.col.f32.f16.f16.f32 "
                 "{%0,%1,%2,%3}, {%4,%5,%6,%7}, {%8,%9}, {%0,%1,%2,%3};"
                 : "+f"(c[0]), "+f"(c[1]), "+f"(c[2]), "+f"(c[3])
                 : "r"(a[0]), "r"(a[1]), "r"(a[2]), "r"(a[3]), "r"(b[0]), "r"(b[1]));
}
__device__ __forceinline__ uint32_t pack_h(float x, float y) {
    __half2 t;
    t.x = __float2half(x);
    t.y = __float2half(y);
    return *(uint32_t*)&t;
}
__device__ __forceinline__ uint32_t pack_h_lo(float x, float y, uint32_t hi) {
    __half2 h = *(__half2*)&hi;
    return pack_h(x - __half2float(h.x), y - __half2float(h.y));
}

// ---------------- Scratch (device globals) ----------------
__device__ __align__(256) float g_Q[(size_t)BSn * QDIM];
__device__ __align__(256) float g_K[(size_t)BSn * KVDIM];
__device__ __align__(256) float g_V[(size_t)BSn * KVDIM];

__device__ __align__(256) fp16 g_Xh[(size_t)BSn * HIDn];
__device__ __align__(256) fp16 g_Xl[(size_t)BSn * HIDn];
__device__ __align__(256) fp16 g_Wqf[(size_t)QDIM * HIDn];
__device__ __align__(256) fp16 g_Wkf[(size_t)KVDIM * HIDn];
__device__ __align__(256) fp16 g_Wvf[(size_t)KVDIM * HIDn];
__device__ __align__(256) fp16 g_Wof[(size_t)HIDn * QDIM];
__device__ __align__(256) fp16 g_Qh[(size_t)BSn * QDIM];
__device__ __align__(256) fp16 g_Ql[(size_t)BSn * QDIM];
__device__ __align__(256) fp16 g_Kf[(size_t)BSn * KVDIM];
__device__ __align__(256) fp16 g_Vt[(size_t)Bn * KVDIM * Sn];
__device__ __align__(256) fp16 g_Ah[(size_t)BSn * QDIM];
__device__ __align__(256) fp16 g_Al[(size_t)BSn * QDIM];

// ================= 2-pass split-fp16 mma.sync GEMM =================
// C[M,N] = (Ah+Al)[M,K] @ Bf[N,K]^T   (both K-major), 3-stage cp.async.
#define PITCHB   80
#define TILE_B   (128 * PITCHB)
#define OFF_AH   0
#define OFF_AL   (TILE_B)
#define OFF_B    (2 * TILE_B)
#define STAGE_B  (3 * TILE_B)          // 30720
#define GSMEM_BYTES (3 * STAGE_B)      // 92160

__global__ void __launch_bounds__(256, 1)
gemm_2p(const fp16* __restrict__ Ah, const fp16* __restrict__ Al,
        const fp16* __restrict__ Bf, float* __restrict__ C,
        int lda, int ldb, int ldc, int K)
{
    extern __shared__ __align__(128) char smem[];
    const int row0 = blockIdx.y * 128;
    const int col0 = blockIdx.x * 128;

    const int tid  = threadIdx.x;
    const int lane = tid & 31;
    const int warp = tid >> 5;
    const int wm   = warp >> 2;
    const int wn   = warp & 3;

    float acc[4][4][4];
    #pragma unroll
    for (int i = 0; i < 4; i++)
        #pragma unroll
        for (int j = 0; j < 4; j++)
            #pragma unroll
            for (int q = 0; q < 4; q++)
                acc[i][j][q] = 0.0f;

    const uint32_t sbase = smem_u32(smem);
    const int nch = K >> 5;

    auto load_stage = [&](int st_idx, int k0) {
        char* st = smem + st_idx * STAGE_B;
        #pragma unroll
        for (int ii = 0; ii < 2; ii++) {
            int i = tid + ii * 256;
            int r = i >> 2, c = i & 3;
            uint32_t dof = (uint32_t)(r * PITCHB + c * 16);
            size_t ga = (size_t)(row0 + r) * lda + k0 + c * 8;
            size_t gb = (size_t)(col0 + r) * ldb + k0 + c * 8;
            cp_async16(smem_u32(st + OFF_AH + dof), Ah + ga);
            cp_async16(smem_u32(st + OFF_AL + dof), Al + ga);
            cp_async16(smem_u32(st + OFF_B + dof),  Bf + gb);
        }
        cp_commit();
    };

    load_stage(0, 0);
    if (nch > 1) load_stage(1, 32);

    int sidx = 0;
    for (int ch = 0; ch < nch; ch++) {
        if (ch + 2 < nch) {
            load_stage((sidx + 2) % 3, (ch + 2) << 5);
            cp_wait<2>();
        } else if (ch + 1 < nch) {
            cp_wait<1>();
        } else {
            cp_wait<0>();
        }
        __syncthreads();

        const uint32_t st = sbase + (uint32_t)(sidx * STAGE_B);

        #pragma unroll
        for (int kk = 0; kk < 32; kk += 16) {
            uint32_t ah[4][4], al[4][4];
            #pragma unroll
            for (int ma = 0; ma < 4; ma++) {
                uint32_t arow = (uint32_t)(wm * 64 + ma * 16 + (lane & 15));
                uint32_t acol = (uint32_t)((kk + ((lane >> 4) << 3)) * 2);
                ldmat4(ah[ma], st + OFF_AH + arow * PITCHB + acol);
                ldmat4(al[ma], st + OFF_AL + arow * PITCHB + acol);
            }
            uint32_t bb[4][2];
            #pragma unroll
            for (int nb = 0; nb < 2; nb++) {
                uint32_t brow = (uint32_t)(wn * 32 + nb * 16 + ((lane >> 4) << 3) + (lane & 7));
                uint32_t bcol = (uint32_t)((kk + (((lane >> 3) & 1) << 3)) * 2);
                uint32_t rh[4];
                ldmat4(rh, st + OFF_B + brow * PITCHB + bcol);
                bb[2 * nb][0] = rh[0]; bb[2 * nb][1] = rh[1];
                bb[2 * nb + 1][0] = rh[2]; bb[2 * nb + 1][1] = rh[3];
            }
            #pragma unroll
            for (int ma = 0; ma < 4; ma++)
                #pragma unroll
                for (int na = 0; na < 4; na++) {
                    mma16816(acc[ma][na], ah[ma], bb[na]);
                    mma16816(acc[ma][na], al[ma], bb[na]);
                }
        }
        __syncthreads();
        sidx = (sidx + 1) % 3;
    }

    #pragma unroll
    for (int ma = 0; ma < 4; ma++) {
        int gr = row0 + wm * 64 + ma * 16 + (lane >> 2);
        #pragma unroll
        for (int na = 0; na < 4; na++) {
            int gc = col0 + wn * 32 + na * 8 + (lane & 3) * 2;
            float2 v0, v1;
            v0.x = acc[ma][na][0];
            v0.y = acc[ma][na][1];
            v1.x = acc[ma][na][2];
            v1.y = acc[ma][na][3];
            *(float2*)(C + (size_t)gr * ldc + gc)       = v0;
            *(float2*)(C + (size_t)(gr + 8) * ldc + gc) = v1;
        }
    }
}

// ================= Fused flash attention (2-pass fp16) =================
// Per CTA: (b, h, row-tile i). S = (Qh+Ql)@Kf^T; online softmax; P split
// in-register; O += (Ph+Pl)@Vf. Writes split-fp16 attention output.
#define FPITCH 272
#define FT     (128 * FPITCH)          // 34816
#define FOFF_QH 0
#define FOFF_QL (FT)
#define FOFF_K  (2 * FT)
#define FOFF_V  (3 * FT)
#define FSMEM_BYTES (4 * FT)           // 139264

__global__ void __launch_bounds__(256, 1)
flash_kernel(const fp16* __restrict__ Qh, const fp16* __restrict__ Ql,
             const fp16* __restrict__ Kf, const fp16* __restrict__ Vf,
             fp16* __restrict__ Ah, fp16* __restrict__ Al)
{
    extern __shared__ __align__(128) char smem[];
    const int i    = 15 - blockIdx.x;      // heavy row tiles first
    const int bh   = blockIdx.y;
    const int b    = bh >> 4, h = bh & 15, kv = h >> 2;
    const int row0 = i * 128;
    const int bSn  = b * Sn;
    const int kvoff = kv * DHn;
    const size_t vbase = (size_t)b * KVDIM * Sn;

    const int tid  = threadIdx.x;
    const int lane = tid & 31;
    const int warp = tid >> 5;
    const int w16  = warp * 16;

    const uint32_t sb = smem_u32(smem);
    const uint32_t sQh = sb + FOFF_QH, sQl = sb + FOFF_QL;
    const uint32_t sK  = sb + FOFF_K,  sV  = sb + FOFF_V;

    auto ldQ = [&]() {
        #pragma unroll
        for (int ii = 0; ii < 8; ii++) {
            int id = tid + ii * 256;
            int r = id >> 4, c = id & 15;
            uint32_t so = (uint32_t)(r * FPITCH + c * 16);
            size_t g = (size_t)(bSn + row0 + r) * QDIM + h * DHn + c * 8;
            cp_async16(sQh + so, Qh + g);
            cp_async16(sQl + so, Ql + g);
        }
    };
    auto ldK = [&](int j0) {
        #pragma unroll
        for (int ii = 0; ii < 8; ii++) {
            int id = tid + ii * 256;
            int r = id >> 4, c = id & 15;
            uint32_t so = (uint32_t)(r * FPITCH + c * 16);
            size_t g = (size_t)(bSn + j0 + r) * KVDIM + kvoff + c * 8;
            cp_async16(sK + so, Kf + g);
        }
    };
    auto ldV = [&](int j0) {
        #pragma unroll
        for (int ii = 0; ii < 8; ii++) {
            int id = tid + ii * 256;
            int r = id >> 4, c = id & 15;
            uint32_t so = (uint32_t)(r * FPITCH + c * 16);
            size_t g = vbase + (size_t)(kvoff + r) * Sn + j0 + c * 8;
            cp_async16(sV + so, Vf + g);
        }
    };

    float o[16][4];
    #pragma unroll
    for (int nt = 0; nt < 16; nt++)
        #pragma unroll
        for (int q = 0; q < 4; q++) o[nt][q] = 0.0f;
    float m0 = -INFINITY, m1 = -INFINITY, l0 = 0.0f, l1 = 0.0f;

    ldQ();
    ldK(0);
    cp_commit();                       // group: Q + K0

    for (int j = 0; j <= i; j++) {
        const int j0 = j << 7;
        ldV(j0);
        cp_commit();                   // group: V_j
        cp_wait<1>();                  // K_j (and Q) ready
        __syncthreads();

        // ---- S = (Qh+Ql) @ K^T ----
        float s[16][4];
        #pragma unroll
        for (int nt = 0; nt < 16; nt++)
            #pragma unroll
            for (int q = 0; q < 4; q++) s[nt][q] = 0.0f;

        #pragma unroll
        for (int kk = 0; kk < 8; kk++) {
            uint32_t aH[4], aL[4];
            uint32_t aoff = (uint32_t)((w16 + (lane & 15)) * FPITCH +
                                       (kk * 16 + ((lane >> 4) << 3)) * 2);
            ldmat4(aH, sQh + aoff);
            ldmat4(aL, sQl + aoff);
            #pragma unroll
            for (int np = 0; np < 8; np++) {
                uint32_t brow = (uint32_t)(np * 16 + ((lane >> 4) << 3) + (lane & 7));
                uint32_t boff = brow * FPITCH +
                                (uint32_t)((kk * 16 + (((lane >> 3) & 1) << 3)) * 2);
                uint32_t rh[4];
                ldmat4(rh, sK + boff);
                uint32_t b0[2] = {rh[0], rh[1]}, b1[2] = {rh[2], rh[3]};
                mma16816(s[2 * np],     aH, b0);
                mma16816(s[2 * np],     aL, b0);
                mma16816(s[2 * np + 1], aH, b1);
                mma16816(s[2 * np + 1], aL, b1);
            }
        }

        __syncthreads();               // all warps done reading K smem
        if (j < i) ldK(j0 + 128);
        cp_commit();                   // group: K_{j+1}

        // ---- online softmax ----
        const int grow0 = row0 + w16 + (lane >> 2);
        const bool diag = (j == i);
        float nm0 = -INFINITY, nm1 = -INFINITY;
        #pragma unroll
        for (int nt = 0; nt < 16; nt++) {
            #pragma unroll
            for (int q = 0; q < 4; q++) {
                float v = s[nt][q] * SCALE;
                if (diag) {
                    int col = j0 + nt * 8 + (lane & 3) * 2 + (q & 1);
                    int gr = (q < 2) ? grow0 : grow0 + 8;
                    if (col > gr) v = -INFINITY;
                }
                s[nt][q] = v;
            }
            nm0 = fmaxf(nm0, fmaxf(s[nt][0], s[nt][1]));
            nm1 = fmaxf(nm1, fmaxf(s[nt][2], s[nt][3]));
        }
        nm0 = fmaxf(nm0, __shfl_xor_sync(0xFFFFFFFFu, nm0, 1));
        nm0 = fmaxf(nm0, __shfl_xor_sync(0xFFFFFFFFu, nm0, 2));
        nm1 = fmaxf(nm1, __shfl_xor_sync(0xFFFFFFFFu, nm1, 1));
        nm1 = fmaxf(nm1, __shfl_xor_sync(0xFFFFFFFFu, nm1, 2));

        float mn0 = fmaxf(m0, nm0), mn1 = fmaxf(m1, nm1);
        float f0 = (m0 > -1e30f) ? __expf(m0 - mn0) : 0.0f;
        float f1 = (m1 > -1e30f) ? __expf(m1 - mn1) : 0.0f;
        m0 = mn0; m1 = mn1;

        float rs0 = 0.0f, rs1 = 0.0f;
        #pragma unroll
        for (int nt = 0; nt < 16; nt++) {
            float p0 = __expf(s[nt][0] - mn0);
            float p1 = __expf(s[nt][1] - mn0);
            float p2 = __expf(s[nt][2] - mn1);
            float p3 = __expf(s[nt][3] - mn1);
            s[nt][0] = p0; s[nt][1] = p1; s[nt][2] = p2; s[nt][3] = p3;
            rs0 += p0 + p1;
            rs1 += p2 + p3;
        }
        rs0 += __shfl_xor_sync(0xFFFFFFFFu, rs0, 1);
        rs0 += __shfl_xor_sync(0xFFFFFFFFu, rs0, 2);
        rs1 += __shfl_xor_sync(0xFFFFFFFFu, rs1, 1);
        rs1 += __shfl_xor_sync(0xFFFFFFFFu, rs1, 2);
        l0 = l0 * f0 + rs0;
        l1 = l1 * f1 + rs1;
        #pragma unroll
        for (int nt = 0; nt < 16; nt++) {
            o[nt][0] *= f0; o[nt][1] *= f0;
            o[nt][2] *= f1; o[nt][3] *= f1;
        }

        cp_wait<1>();                  // V_j ready
        __syncthreads();

        // ---- O += (Ph+Pl) @ V ----
        #pragma unroll
        for (int kk = 0; kk < 8; kk++) {
            uint32_t pH[4], pL[4];
            pH[0] = pack_h(s[2 * kk][0],     s[2 * kk][1]);
            pH[1] = pack_h(s[2 * kk][2],     s[2 * kk][3]);
            pH[2] = pack_h(s[2 * kk + 1][0], s[2 * kk + 1][1]);
            pH[3] = pack_h(s[2 * kk + 1][2], s[2 * kk + 1][3]);
            pL[0] = pack_h_lo(s[2 * kk][0],     s[2 * kk][1],     pH[0]);
            pL[1] = pack_h_lo(s[2 * kk][2],     s[2 * kk][3],     pH[1]);
            pL[2] = pack_h_lo(s[2 * kk + 1][0], s[2 * kk + 1][1], pH[2]);
            pL[3] = pack_h_lo(s[2 * kk + 1][2], s[2 * kk + 1][3], pH[3]);
            #pragma unroll
            for (int np = 0; np < 8; np++) {
                uint32_t brow = (uint32_t)(np * 16 + ((lane >> 4) << 3) + (lane & 7));
                uint32_t boff = brow * FPITCH +
                                (uint32_t)((kk * 16 + (((lane >> 3) & 1) << 3)) * 2);
                uint32_t rh[4];
                ldmat4(rh, sV + boff);
                uint32_t b0[2] = {rh[0], rh[1]}, b1[2] = {rh[2], rh[3]};
                mma16816(o[2 * np],     pH, b0);
                mma16816(o[2 * np],     pL, b0);
                mma16816(o[2 * np + 1], pH, b1);
                mma16816(o[2 * np + 1], pL, b1);
            }
        }
        __syncthreads();               // all warps done reading V smem
    }

    // ---- epilogue: out = O / l, split fp16 hi/lo ----
    const float inv0 = 1.0f / l0, inv1 = 1.0f / l1;
    const int gr0 = bSn + row0 + w16 + (lane >> 2);
    const size_t cbase = (size_t)h * DHn + (lane & 3) * 2;
    #pragma unroll
    for (int nt = 0; nt < 16; nt++) {
        size_t i0 = (size_t)gr0 * QDIM + cbase + nt * 8;
        size_t i1 = (size_t)(gr0 + 8) * QDIM + cbase + nt * 8;
        float v0 = o[nt][0] * inv0, v1 = o[nt][1] * inv0;
        float v2 = o[nt][2] * inv1, v3 = o[nt][3] * inv1;
        uint32_t h0 = pack_h(v0, v1);
        uint32_t h1 = pack_h(v2, v3);
        *(uint32_t*)(Ah + i0) = h0;
        *(uint32_t*)(Ah + i1) = h1;
        *(uint32_t*)(Al + i0) = pack_h_lo(v0, v1, h0);
        *(uint32_t*)(Al + i1) = pack_h_lo(v2, v3, h1);
    }
}

// ---------------- Elementwise split: x -> hi + lo (fp16) ----------------
__global__ void split_plain(const float* __restrict__ x, fp16* __restrict__ h,
                            fp16* __restrict__ l, int n)
{
    for (int i = blockIdx.x * blockDim.x + threadIdx.x; i < n; i += gridDim.x * blockDim.x) {
        float v = x[i];
        fp16 hi = __float2half(v);
        h[i] = hi;
        l[i] = __float2half(v - __half2float(hi));
    }
}

// ---------------- Transpose: src[R,C] f32 -> dst[C,R] fp16 ----------------
__global__ void half_transpose(const float* __restrict__ src, fp16* __restrict__ dst,
                               int R, int C, long sS, long sD)
{
    __shared__ float t[32][33];
    src += (size_t)blockIdx.z * sS;
    dst += (size_t)blockIdx.z * sD;
    int c0 = blockIdx.x * 32, r0 = blockIdx.y * 32;
    int tx = threadIdx.x, ty = threadIdx.y;
    #pragma unroll
    for (int i = 0; i < 4; i++)
        t[ty + i * 8][tx] = src[(size_t)(r0 + ty + i * 8) * C + c0 + tx];
    __syncthreads();
    #pragma unroll
    for (int i = 0; i < 4; i++)
        dst[(size_t)(c0 + ty + i * 8) * R + r0 + tx] = __float2half(t[tx][ty + i * 8]);
}

// ---------------- Fused RMSNorm + RoPE -> fp16 (split if xl != null) ------
__global__ void norm_rope_split(const float* __restrict__ x, const float* __restrict__ w,
                                const float* __restrict__ cosp, const float* __restrict__ sinp,
                                fp16* __restrict__ xh, fp16* __restrict__ xl, int nheads)
{
    int warp = (blockIdx.x * blockDim.x + threadIdx.x) >> 5;
    int lane = threadIdx.x & 31;
    if (warp >= BSn * nheads) return;
    int h  = warp % nheads;
    int bs = warp / nheads;
    int s  = bs & (Sn - 1);

    size_t base = (size_t)bs * nheads * DHn + (size_t)h * DHn;
    const float* row = x + base;
    float v0 = row[lane];
    float v1 = row[lane + 32];
    float v2 = row[lane + 64];
    float v3 = row[lane + 96];

    float ss = v0 * v0 + v1 * v1 + v2 * v2 + v3 * v3;
    #pragma unroll
    for (int o = 16; o > 0; o >>= 1) ss += __shfl_xor_sync(0xFFFFFFFFu, ss, o);
    float r = rsqrtf(ss * (1.0f / 128.0f) + 1e-6f);

    v0 = v0 * r * w[lane];
    v1 = v1 * r * w[lane + 32];
    v2 = v2 * r * w[lane + 64];
    v3 = v3 * r * w[lane + 96];

    const float* cs = cosp + (size_t)s * DHn;
    const float* sn = sinp + (size_t)s * DHn;
    float o0 = v0 * cs[lane]      - v2 * sn[lane];
    float o1 = v1 * cs[lane + 32] - v3 * sn[lane + 32];
    float o2 = v2 * cs[lane + 64] + v0 * sn[lane + 64];
    float o3 = v3 * cs[lane + 96] + v1 * sn[lane + 96];

    #pragma unroll
    for (int q = 0; q < 4; q++) {
        float ov = (q == 0) ? o0 : (q == 1) ? o1 : (q == 2) ? o2 : o3;
        size_t idx = base + lane + q * 32;
        fp16 hi = __float2half(ov);
        xh[idx] = hi;
        if (xl) xl[idx] = __float2half(ov - __half2float(hi));
    }
}

// ---------------- Launch ----------------
extern "C" void kernel_launch(void* const* d_in, const int* in_sizes, int n_in,
                              void* d_out, int out_size)
{
    (void)in_sizes; (void)n_in; (void)out_size;
    const float* X    = (const float*)d_in[0];
    const float* cosp = (const float*)d_in[2];
    const float* sinp = (const float*)d_in[3];
    const float* Wq   = (const float*)d_in[4];
    const float* Wk   = (const float*)d_in[5];
    const float* Wv   = (const float*)d_in[6];
    const float* Wo   = (const float*)d_in[7];
    const float* qw   = (const float*)d_in[8];
    const float* kw   = (const float*)d_in[9];
    float* out = (float*)d_out;

    cudaFuncSetAttribute(gemm_2p, cudaFuncAttributeMaxDynamicSharedMemorySize, GSMEM_BYTES);
    cudaFuncSetAttribute(flash_kernel, cudaFuncAttributeMaxDynamicSharedMemorySize, FSMEM_BYTES);

    void *p;
    #define SYM(v, s) cudaGetSymbolAddress(&p, s); auto v = (decltype(&s[0]))p;
    SYM(Q,  g_Q)   SYM(Kr, g_K)   SYM(Vr, g_V)
    SYM(Xh, g_Xh)  SYM(Xl, g_Xl)
    SYM(Wqf, g_Wqf) SYM(Wkf, g_Wkf) SYM(Wvf, g_Wvf) SYM(Wof, g_Wof)
    SYM(Qh, g_Qh)  SYM(Ql, g_Ql)  SYM(Kf, g_Kf)  SYM(Vt, g_Vt)
    SYM(Ah, g_Ah)  SYM(Al, g_Al)
    #undef SYM

    // 0) X split; weights -> transposed single fp16 [N,K]
    split_plain<<<2048, 256>>>(X, Xh, Xl, BSn * HIDn);
    half_transpose<<<dim3(QDIM / 32, HIDn / 32, 1), dim3(32, 8)>>>(Wq, Wqf, HIDn, QDIM, 0, 0);
    half_transpose<<<dim3(KVDIM / 32, HIDn / 32, 1), dim3(32, 8)>>>(Wk, Wkf, HIDn, KVDIM, 0, 0);
    half_transpose<<<dim3(KVDIM / 32, HIDn / 32, 1), dim3(32, 8)>>>(Wv, Wvf, HIDn, KVDIM, 0, 0);
    half_transpose<<<dim3(HIDn / 32, QDIM / 32, 1), dim3(32, 8)>>>(Wo, Wof, QDIM, HIDn, 0, 0);

    // 1) Projections (fp32 outputs)
    gemm_2p<<<dim3(QDIM / 128, BSn / 128), 256, GSMEM_BYTES>>>(
        Xh, Xl, Wqf, Q, HIDn, HIDn, QDIM, HIDn);
    gemm_2p<<<dim3(KVDIM / 128, BSn / 128), 256, GSMEM_BYTES>>>(
        Xh, Xl, Wkf, Kr, HIDn, HIDn, KVDIM, HIDn);
    gemm_2p<<<dim3(KVDIM / 128, BSn / 128), 256, GSMEM_BYTES>>>(
        Xh, Xl, Wvf, Vr, HIDn, HIDn, KVDIM, HIDn);

    // 2) RMSNorm+RoPE: Q -> split, K -> single;  V -> transposed [b][kv*dh][s]
    norm_rope_split<<<(BSn * NHn) / 8, 256>>>(Q, qw, cosp, sinp, Qh, Ql, NHn);
    norm_rope_split<<<(BSn * NKVn) / 8, 256>>>(Kr, kw, cosp, sinp, Kf, (fp16*)0, NKVn);
    half_transpose<<<dim3(KVDIM / 32, Sn / 32, Bn), dim3(32, 8)>>>(
        Vr, Vt, Sn, KVDIM, (long)Sn * KVDIM, (long)KVDIM * Sn);

    // 3) Fused flash attention -> split fp16 output
    flash_kernel<<<dim3(Sn / 128, Bn * NHn), 256, FSMEM_BYTES>>>(
        Qh, Ql, Kf, Vt, Ah, Al);

    // 4) Output projection
    gemm_2p<<<dim3(HIDn / 128, BSn / 128), 256, GSMEM_BYTES>>>(
        Ah, Al, Wof, out, QDIM, QDIM, HIDn, QDIM);
}

// round 6
// speedup vs baseline: 8.4283x; 1.7739x over previous
#include <cuda_runtime.h>
#include <cuda_fp16.h>
#include <math.h>
#include <stdint.h>

// ---------------- Problem constants ----------------
#define Bn   2
#define Sn   2048
#define HIDn 2048
#define NHn  16
#define NKVn 4
#define DHn  128
#define BSn  (Bn * Sn)           // 4096
#define QDIM (NHn * DHn)         // 2048
#define KVDIM (NKVn * DHn)       // 512
#define SCALE 0.08838834764831845f

typedef __half fp16;

// ---------------- PTX helpers (base ISA, sm_80+) ----------------
__device__ __forceinline__ uint32_t smem_u32(const void* p) {
    uint32_t a;
    asm("{ .reg .u64 t; cvta.to.shared.u64 t, %1; cvt.u32.u64 %0, t; }" : "=r"(a) : "l"(p));
    return a;
}
__device__ __forceinline__ void cp_async16(uint32_t saddr, const void* gaddr) {
    asm volatile("cp.async.cg.shared.global [%0], [%1], 16;" :: "r"(saddr), "l"(gaddr));
}
__device__ __forceinline__ void cp_commit() {
    asm volatile("cp.async.commit_group;" ::: "memory");
}
template <int N>
__device__ __forceinline__ void cp_wait() {
    asm volatile("cp.async.wait_group %0;" :: "n"(N) : "memory");
}
__device__ __forceinline__ void ldmat4(uint32_t* r, uint32_t addr) {
    asm volatile("ldmatrix.sync.aligned.m8n8.x4.shared.b16 {%0,%1,%2,%3}, [%4];"
                 : "=r"(r[0]), "=r"(r[1]), "=r"(r[2]), "=r"(r[3]) : "r"(addr));
}
__device__ __forceinline__ void mma16816(float* c, const uint32_t* a, const uint32_t* b) {
    asm volatile("mma.sync.aligned.m16n8k16.row.col.f32.f16.f16.f32 "
                 "{%0,%1,%2,%3}, {%4,%5,%6,%7}, {%8,%9}, {%0,%1,%2,%3};"
                 : "+f"(c[0]), "+f"(c[1]), "+f"(c[2]), "+f"(c[3])
                 : "r"(a[0]), "r"(a[1]), "r"(a[2]), "r"(a[3]), "r"(b[0]), "r"(b[1]));
}
__device__ __forceinline__ uint32_t pack_h(float x, float y) {
    __half2 t;
    t.x = __float2half(x);
    t.y = __float2half(y);
    return *(uint32_t*)&t;
}

// ---------------- Scratch (device globals) ----------------
__device__ __align__(256) float g_Q[(size_t)BSn * QDIM];
__device__ __align__(256) float g_K[(size_t)BSn * KVDIM];
__device__ __align__(256) float g_V[(size_t)BSn * KVDIM];

__device__ __align__(256) fp16 g_Xf[(size_t)BSn * HIDn];
__device__ __align__(256) fp16 g_Wqf[(size_t)QDIM * HIDn];
__device__ __align__(256) fp16 g_Wkf[(size_t)KVDIM * HIDn];
__device__ __align__(256) fp16 g_Wvf[(size_t)KVDIM * HIDn];
__device__ __align__(256) fp16 g_Wof[(size_t)HIDn * QDIM];
__device__ __align__(256) fp16 g_Qf[(size_t)BSn * QDIM];
__device__ __align__(256) fp16 g_Kf[(size_t)BSn * KVDIM];
__device__ __align__(256) fp16 g_Vt[(size_t)Bn * KVDIM * Sn];
__device__ __align__(256) fp16 g_Af[(size_t)BSn * QDIM];

// ================= Single-pass fp16 mma.sync GEMM =================
// C[M,N] = Af[M,K] @ Bf[N,K]^T   (both K-major), 3-stage cp.async,
// 128x128 tile, BK=32, 256 threads, warp 64x32.
#define PITCHB   80
#define TILE_B   (128 * PITCHB)
#define OFF_A    0
#define OFF_B    (TILE_B)
#define STAGE_B  (2 * TILE_B)          // 20480
#define GSMEM_BYTES (3 * STAGE_B)      // 61440

__global__ void __launch_bounds__(256, 2)
gemm_1p(const fp16* __restrict__ Af, const fp16* __restrict__ Bf,
        float* __restrict__ C, int lda, int ldb, int ldc, int K)
{
    extern __shared__ __align__(128) char smem[];
    const int row0 = blockIdx.y * 128;
    const int col0 = blockIdx.x * 128;

    const int tid  = threadIdx.x;
    const int lane = tid & 31;
    const int warp = tid >> 5;
    const int wm   = warp >> 2;
    const int wn   = warp & 3;

    float acc[4][4][4];
    #pragma unroll
    for (int i = 0; i < 4; i++)
        #pragma unroll
        for (int j = 0; j < 4; j++)
            #pragma unroll
            for (int q = 0; q < 4; q++)
                acc[i][j][q] = 0.0f;

    const uint32_t sbase = smem_u32(smem);
    const int nch = K >> 5;

    auto load_stage = [&](int st_idx, int k0) {
        char* st = smem + st_idx * STAGE_B;
        #pragma unroll
        for (int ii = 0; ii < 2; ii++) {
            int i = tid + ii * 256;        // 0..511
            int r = i >> 2, c = i & 3;
            uint32_t dof = (uint32_t)(r * PITCHB + c * 16);
            cp_async16(smem_u32(st + OFF_A + dof), Af + (size_t)(row0 + r) * lda + k0 + c * 8);
            cp_async16(smem_u32(st + OFF_B + dof), Bf + (size_t)(col0 + r) * ldb + k0 + c * 8);
        }
        cp_commit();
    };

    load_stage(0, 0);
    if (nch > 1) load_stage(1, 32);

    int sidx = 0;
    for (int ch = 0; ch < nch; ch++) {
        if (ch + 2 < nch) {
            load_stage((sidx + 2) % 3, (ch + 2) << 5);
            cp_wait<2>();
        } else if (ch + 1 < nch) {
            cp_wait<1>();
        } else {
            cp_wait<0>();
        }
        __syncthreads();

        const uint32_t st = sbase + (uint32_t)(sidx * STAGE_B);

        #pragma unroll
        for (int kk = 0; kk < 32; kk += 16) {
            uint32_t ah[4][4];
            #pragma unroll
            for (int ma = 0; ma < 4; ma++) {
                uint32_t arow = (uint32_t)(wm * 64 + ma * 16 + (lane & 15));
                uint32_t acol = (uint32_t)((kk + ((lane >> 4) << 3)) * 2);
                ldmat4(ah[ma], st + OFF_A + arow * PITCHB + acol);
            }
            uint32_t bb[4][2];
            #pragma unroll
            for (int nb = 0; nb < 2; nb++) {
                uint32_t brow = (uint32_t)(wn * 32 + nb * 16 + ((lane >> 4) << 3) + (lane & 7));
                uint32_t bcol = (uint32_t)((kk + (((lane >> 3) & 1) << 3)) * 2);
                uint32_t rh[4];
                ldmat4(rh, st + OFF_B + brow * PITCHB + bcol);
                bb[2 * nb][0] = rh[0]; bb[2 * nb][1] = rh[1];
                bb[2 * nb + 1][0] = rh[2]; bb[2 * nb + 1][1] = rh[3];
            }
            #pragma unroll
            for (int ma = 0; ma < 4; ma++)
                #pragma unroll
                for (int na = 0; na < 4; na++)
                    mma16816(acc[ma][na], ah[ma], bb[na]);
        }
        __syncthreads();
        sidx = (sidx + 1) % 3;
    }

    #pragma unroll
    for (int ma = 0; ma < 4; ma++) {
        int gr = row0 + wm * 64 + ma * 16 + (lane >> 2);
        #pragma unroll
        for (int na = 0; na < 4; na++) {
            int gc = col0 + wn * 32 + na * 8 + (lane & 3) * 2;
            float2 v0, v1;
            v0.x = acc[ma][na][0];
            v0.y = acc[ma][na][1];
            v1.x = acc[ma][na][2];
            v1.y = acc[ma][na][3];
            *(float2*)(C + (size_t)gr * ldc + gc)       = v0;
            *(float2*)(C + (size_t)(gr + 8) * ldc + gc) = v1;
        }
    }
}

// ================= Fused flash attention (single-pass fp16) =================
#define FPITCH 272
#define FT     (128 * FPITCH)          // 34816
#define FOFF_Q 0
#define FOFF_K (FT)
#define FOFF_V (2 * FT)
#define FSMEM_BYTES (3 * FT)           // 104448

__global__ void __launch_bounds__(256, 1)
flash_kernel(const fp16* __restrict__ Qf, const fp16* __restrict__ Kf,
             const fp16* __restrict__ Vf, fp16* __restrict__ Af)
{
    extern __shared__ __align__(128) char smem[];
    const int i    = 15 - blockIdx.x;      // heavy row tiles first
    const int bh   = blockIdx.y;
    const int b    = bh >> 4, h = bh & 15, kv = h >> 2;
    const int row0 = i * 128;
    const int bSn  = b * Sn;
    const int kvoff = kv * DHn;
    const size_t vbase = (size_t)b * KVDIM * Sn;

    const int tid  = threadIdx.x;
    const int lane = tid & 31;
    const int warp = tid >> 5;
    const int w16  = warp * 16;

    const uint32_t sb = smem_u32(smem);
    const uint32_t sQ = sb + FOFF_Q, sK = sb + FOFF_K, sV = sb + FOFF_V;

    auto ldQ = [&]() {
        #pragma unroll
        for (int ii = 0; ii < 8; ii++) {
            int id = tid + ii * 256;
            int r = id >> 4, c = id & 15;
            cp_async16(sQ + (uint32_t)(r * FPITCH + c * 16),
                       Qf + (size_t)(bSn + row0 + r) * QDIM + h * DHn + c * 8);
        }
    };
    auto ldK = [&](int j0) {
        #pragma unroll
        for (int ii = 0; ii < 8; ii++) {
            int id = tid + ii * 256;
            int r = id >> 4, c = id & 15;
            cp_async16(sK + (uint32_t)(r * FPITCH + c * 16),
                       Kf + (size_t)(bSn + j0 + r) * KVDIM + kvoff + c * 8);
        }
    };
    auto ldV = [&](int j0) {
        #pragma unroll
        for (int ii = 0; ii < 8; ii++) {
            int id = tid + ii * 256;
            int r = id >> 4, c = id & 15;
            cp_async16(sV + (uint32_t)(r * FPITCH + c * 16),
                       Vf + vbase + (size_t)(kvoff + r) * Sn + j0 + c * 8);
        }
    };

    float o[16][4];
    #pragma unroll
    for (int nt = 0; nt < 16; nt++)
        #pragma unroll
        for (int q = 0; q < 4; q++) o[nt][q] = 0.0f;
    float m0 = -INFINITY, m1 = -INFINITY, l0 = 0.0f, l1 = 0.0f;

    ldQ();
    ldK(0);
    cp_commit();                       // group: Q + K0

    for (int j = 0; j <= i; j++) {
        const int j0 = j << 7;
        ldV(j0);
        cp_commit();                   // group: V_j
        cp_wait<1>();                  // K_j (and Q) ready
        __syncthreads();

        // ---- S = Q @ K^T ----
        float s[16][4];
        #pragma unroll
        for (int nt = 0; nt < 16; nt++)
            #pragma unroll
            for (int q = 0; q < 4; q++) s[nt][q] = 0.0f;

        #pragma unroll
        for (int kk = 0; kk < 8; kk++) {
            uint32_t aH[4];
            uint32_t aoff = (uint32_t)((w16 + (lane & 15)) * FPITCH +
                                       (kk * 16 + ((lane >> 4) << 3)) * 2);
            ldmat4(aH, sQ + aoff);
            #pragma unroll
            for (int np = 0; np < 8; np++) {
                uint32_t brow = (uint32_t)(np * 16 + ((lane >> 4) << 3) + (lane & 7));
                uint32_t boff = brow * FPITCH +
                                (uint32_t)((kk * 16 + (((lane >> 3) & 1) << 3)) * 2);
                uint32_t rh[4];
                ldmat4(rh, sK + boff);
                uint32_t b0[2] = {rh[0], rh[1]}, b1[2] = {rh[2], rh[3]};
                mma16816(s[2 * np],     aH, b0);
                mma16816(s[2 * np + 1], aH, b1);
            }
        }

        __syncthreads();               // all warps done reading K smem
        if (j < i) ldK(j0 + 128);
        cp_commit();                   // group: K_{j+1}

        // ---- online softmax ----
        const int grow0 = row0 + w16 + (lane >> 2);
        const bool diag = (j == i);
        float nm0 = -INFINITY, nm1 = -INFINITY;
        #pragma unroll
        for (int nt = 0; nt < 16; nt++) {
            #pragma unroll
            for (int q = 0; q < 4; q++) {
                float v = s[nt][q] * SCALE;
                if (diag) {
                    int col = j0 + nt * 8 + (lane & 3) * 2 + (q & 1);
                    int gr = (q < 2) ? grow0 : grow0 + 8;
                    if (col > gr) v = -INFINITY;
                }
                s[nt][q] = v;
            }
            nm0 = fmaxf(nm0, fmaxf(s[nt][0], s[nt][1]));
            nm1 = fmaxf(nm1, fmaxf(s[nt][2], s[nt][3]));
        }
        nm0 = fmaxf(nm0, __shfl_xor_sync(0xFFFFFFFFu, nm0, 1));
        nm0 = fmaxf(nm0, __shfl_xor_sync(0xFFFFFFFFu, nm0, 2));
        nm1 = fmaxf(nm1, __shfl_xor_sync(0xFFFFFFFFu, nm1, 1));
        nm1 = fmaxf(nm1, __shfl_xor_sync(0xFFFFFFFFu, nm1, 2));

        float mn0 = fmaxf(m0, nm0), mn1 = fmaxf(m1, nm1);
        float f0 = (m0 > -1e30f) ? __expf(m0 - mn0) : 0.0f;
        float f1 = (m1 > -1e30f) ? __expf(m1 - mn1) : 0.0f;
        m0 = mn0; m1 = mn1;

        float rs0 = 0.0f, rs1 = 0.0f;
        #pragma unroll
        for (int nt = 0; nt < 16; nt++) {
            float p0 = __expf(s[nt][0] - mn0);
            float p1 = __expf(s[nt][1] - mn0);
            float p2 = __expf(s[nt][2] - mn1);
            float p3 = __expf(s[nt][3] - mn1);
            s[nt][0] = p0; s[nt][1] = p1; s[nt][2] = p2; s[nt][3] = p3;
            rs0 += p0 + p1;
            rs1 += p2 + p3;
        }
        rs0 += __shfl_xor_sync(0xFFFFFFFFu, rs0, 1);
        rs0 += __shfl_xor_sync(0xFFFFFFFFu, rs0, 2);
        rs1 += __shfl_xor_sync(0xFFFFFFFFu, rs1, 1);
        rs1 += __shfl_xor_sync(0xFFFFFFFFu, rs1, 2);
        l0 = l0 * f0 + rs0;
        l1 = l1 * f1 + rs1;
        #pragma unroll
        for (int nt = 0; nt < 16; nt++) {
            o[nt][0] *= f0; o[nt][1] *= f0;
            o[nt][2] *= f1; o[nt][3] *= f1;
        }

        cp_wait<1>();                  // V_j ready
        __syncthreads();

        // ---- O += P @ V ----
        #pragma unroll
        for (int kk = 0; kk < 8; kk++) {
            uint32_t pH[4];
            pH[0] = pack_h(s[2 * kk][0],     s[2 * kk][1]);
            pH[1] = pack_h(s[2 * kk][2],     s[2 * kk][3]);
            pH[2] = pack_h(s[2 * kk + 1][0], s[2 * kk + 1][1]);
            pH[3] = pack_h(s[2 * kk + 1][2], s[2 * kk + 1][3]);
            #pragma unroll
            for (int np = 0; np < 8; np++) {
                uint32_t brow = (uint32_t)(np * 16 + ((lane >> 4) << 3) + (lane & 7));
                uint32_t boff = brow * FPITCH +
                                (uint32_t)((kk * 16 + (((lane >> 3) & 1) << 3)) * 2);
                uint32_t rh[4];
                ldmat4(rh, sV + boff);
                uint32_t b0[2] = {rh[0], rh[1]}, b1[2] = {rh[2], rh[3]};
                mma16816(o[2 * np],     pH, b0);
                mma16816(o[2 * np + 1], pH, b1);
            }
        }
        __syncthreads();               // all warps done reading V smem
    }

    // ---- epilogue: out = O / l -> fp16 ----
    const float inv0 = 1.0f / l0, inv1 = 1.0f / l1;
    const int gr0 = bSn + row0 + w16 + (lane >> 2);
    const size_t cbase = (size_t)h * DHn + (lane & 3) * 2;
    #pragma unroll
    for (int nt = 0; nt < 16; nt++) {
        size_t i0 = (size_t)gr0 * QDIM + cbase + nt * 8;
        size_t i1 = (size_t)(gr0 + 8) * QDIM + cbase + nt * 8;
        *(uint32_t*)(Af + i0) = pack_h(o[nt][0] * inv0, o[nt][1] * inv0);
        *(uint32_t*)(Af + i1) = pack_h(o[nt][2] * inv1, o[nt][3] * inv1);
    }
}

// ---------------- Elementwise cast f32 -> fp16 ----------------
__global__ void cast_plain(const float* __restrict__ x, fp16* __restrict__ y, int n)
{
    for (int i = blockIdx.x * blockDim.x + threadIdx.x; i < n; i += gridDim.x * blockDim.x)
        y[i] = __float2half(x[i]);
}

// ---------------- Transpose: src[R,C] f32 -> dst[C,R] fp16 ----------------
__global__ void half_transpose(const float* __restrict__ src, fp16* __restrict__ dst,
                               int R, int C, long sS, long sD)
{
    __shared__ float t[32][33];
    src += (size_t)blockIdx.z * sS;
    dst += (size_t)blockIdx.z * sD;
    int c0 = blockIdx.x * 32, r0 = blockIdx.y * 32;
    int tx = threadIdx.x, ty = threadIdx.y;
    #pragma unroll
    for (int i = 0; i < 4; i++)
        t[ty + i * 8][tx] = src[(size_t)(r0 + ty + i * 8) * C + c0 + tx];
    __syncthreads();
    #pragma unroll
    for (int i = 0; i < 4; i++)
        dst[(size_t)(c0 + ty + i * 8) * R + r0 + tx] = __float2half(t[tx][ty + i * 8]);
}

// ---------------- Fused RMSNorm + RoPE -> fp16 ----------------
__global__ void norm_rope(const float* __restrict__ x, const float* __restrict__ w,
                          const float* __restrict__ cosp, const float* __restrict__ sinp,
                          fp16* __restrict__ xf, int nheads)
{
    int warp = (blockIdx.x * blockDim.x + threadIdx.x) >> 5;
    int lane = threadIdx.x & 31;
    if (warp >= BSn * nheads) return;
    int h  = warp % nheads;
    int bs = warp / nheads;
    int s  = bs & (Sn - 1);

    size_t base = (size_t)bs * nheads * DHn + (size_t)h * DHn;
    const float* row = x + base;
    float v0 = row[lane];
    float v1 = row[lane + 32];
    float v2 = row[lane + 64];
    float v3 = row[lane + 96];

    float ss = v0 * v0 + v1 * v1 + v2 * v2 + v3 * v3;
    #pragma unroll
    for (int o = 16; o > 0; o >>= 1) ss += __shfl_xor_sync(0xFFFFFFFFu, ss, o);
    float r = rsqrtf(ss * (1.0f / 128.0f) + 1e-6f);

    v0 = v0 * r * w[lane];
    v1 = v1 * r * w[lane + 32];
    v2 = v2 * r * w[lane + 64];
    v3 = v3 * r * w[lane + 96];

    const float* cs = cosp + (size_t)s * DHn;
    const float* sn = sinp + (size_t)s * DHn;
    float o0 = v0 * cs[lane]      - v2 * sn[lane];
    float o1 = v1 * cs[lane + 32] - v3 * sn[lane + 32];
    float o2 = v2 * cs[lane + 64] + v0 * sn[lane + 64];
    float o3 = v3 * cs[lane + 96] + v1 * sn[lane + 96];

    xf[base + lane]      = __float2half(o0);
    xf[base + lane + 32] = __float2half(o1);
    xf[base + lane + 64] = __float2half(o2);
    xf[base + lane + 96] = __float2half(o3);
}

// ---------------- Launch ----------------
extern "C" void kernel_launch(void* const* d_in, const int* in_sizes, int n_in,
                              void* d_out, int out_size)
{
    (void)in_sizes; (void)n_in; (void)out_size;
    const float* X    = (const float*)d_in[0];
    const float* cosp = (const float*)d_in[2];
    const float* sinp = (const float*)d_in[3];
    const float* Wq   = (const float*)d_in[4];
    const float* Wk   = (const float*)d_in[5];
    const float* Wv   = (const float*)d_in[6];
    const float* Wo   = (const float*)d_in[7];
    const float* qw   = (const float*)d_in[8];
    const float* kw   = (const float*)d_in[9];
    float* out = (float*)d_out;

    cudaFuncSetAttribute(gemm_1p, cudaFuncAttributeMaxDynamicSharedMemorySize, GSMEM_BYTES);
    cudaFuncSetAttribute(flash_kernel, cudaFuncAttributeMaxDynamicSharedMemorySize, FSMEM_BYTES);

    void *p;
    #define SYM(v, s) cudaGetSymbolAddress(&p, s); auto v = (decltype(&s[0]))p;
    SYM(Q,  g_Q)   SYM(Kr, g_K)   SYM(Vr, g_V)
    SYM(Xf, g_Xf)
    SYM(Wqf, g_Wqf) SYM(Wkf, g_Wkf) SYM(Wvf, g_Wvf) SYM(Wof, g_Wof)
    SYM(Qf, g_Qf)  SYM(Kf, g_Kf)  SYM(Vt, g_Vt)  SYM(Af, g_Af)
    #undef SYM

    // 0) X -> fp16;  weights -> transposed fp16 [N,K]
    cast_plain<<<2048, 256>>>(X, Xf, BSn * HIDn);
    half_transpose<<<dim3(QDIM / 32, HIDn / 32, 1), dim3(32, 8)>>>(Wq, Wqf, HIDn, QDIM, 0, 0);
    half_transpose<<<dim3(KVDIM / 32, HIDn / 32, 1), dim3(32, 8)>>>(Wk, Wkf, HIDn, KVDIM, 0, 0);
    half_transpose<<<dim3(KVDIM / 32, HIDn / 32, 1), dim3(32, 8)>>>(Wv, Wvf, HIDn, KVDIM, 0, 0);
    half_transpose<<<dim3(HIDn / 32, QDIM / 32, 1), dim3(32, 8)>>>(Wo, Wof, QDIM, HIDn, 0, 0);

    // 1) Projections (fp32 outputs)
    gemm_1p<<<dim3(QDIM / 128, BSn / 128), 256, GSMEM_BYTES>>>(
        Xf, Wqf, Q, HIDn, HIDn, QDIM, HIDn);
    gemm_1p<<<dim3(KVDIM / 128, BSn / 128), 256, GSMEM_BYTES>>>(
        Xf, Wkf, Kr, HIDn, HIDn, KVDIM, HIDn);
    gemm_1p<<<dim3(KVDIM / 128, BSn / 128), 256, GSMEM_BYTES>>>(
        Xf, Wvf, Vr, HIDn, HIDn, KVDIM, HIDn);

    // 2) RMSNorm+RoPE -> fp16 Q/K;  V -> transposed [b][kv*dh][s]
    norm_rope<<<(BSn * NHn) / 8, 256>>>(Q, qw, cosp, sinp, Qf, NHn);
    norm_rope<<<(BSn * NKVn) / 8, 256>>>(Kr, kw, cosp, sinp, Kf, NKVn);
    half_transpose<<<dim3(KVDIM / 32, Sn / 32, Bn), dim3(32, 8)>>>(
        Vr, Vt, Sn, KVDIM, (long)Sn * KVDIM, (long)KVDIM * Sn);

    // 3) Fused flash attention -> fp16 output
    flash_kernel<<<dim3(Sn / 128, Bn * NHn), 256, FSMEM_BYTES>>>(Qf, Kf, Vt, Af);

    // 4) Output projection
    gemm_1p<<<dim3(HIDn / 128, BSn / 128), 256, GSMEM_BYTES>>>(
        Af, Wof, out, QDIM, QDIM, HIDn, QDIM);
}

// round 7
// speedup vs baseline: 8.8015x; 1.0443x over previous
#include <cuda_runtime.h>
#include <cuda_fp16.h>
#include <math.h>
#include <stdint.h>

// ---------------- Problem constants ----------------
#define Bn   2
#define Sn   2048
#define HIDn 2048
#define NHn  16
#define NKVn 4
#define DHn  128
#define BSn  (Bn * Sn)           // 4096
#define QDIM (NHn * DHn)         // 2048
#define KVDIM (NKVn * DHn)       // 512
#define SCALE 0.08838834764831845f

typedef __half fp16;

// ---------------- PTX helpers (base ISA, sm_80+) ----------------
__device__ __forceinline__ uint32_t smem_u32(const void* p) {
    uint32_t a;
    asm("{ .reg .u64 t; cvta.to.shared.u64 t, %1; cvt.u32.u64 %0, t; }" : "=r"(a) : "l"(p));
    return a;
}
__device__ __forceinline__ void cp_async16(uint32_t saddr, const void* gaddr) {
    asm volatile("cp.async.cg.shared.global [%0], [%1], 16;" :: "r"(saddr), "l"(gaddr));
}
__device__ __forceinline__ void cp_commit() {
    asm volatile("cp.async.commit_group;" ::: "memory");
}
template <int N>
__device__ __forceinline__ void cp_wait() {
    asm volatile("cp.async.wait_group %0;" :: "n"(N) : "memory");
}
__device__ __forceinline__ void ldmat4(uint32_t* r, uint32_t addr) {
    asm volatile("ldmatrix.sync.aligned.m8n8.x4.shared.b16 {%0,%1,%2,%3}, [%4];"
                 : "=r"(r[0]), "=r"(r[1]), "=r"(r[2]), "=r"(r[3]) : "r"(addr));
}
__device__ __forceinline__ void mma16816(float* c, const uint32_t* a, const uint32_t* b) {
    asm volatile("mma.sync.aligned.m16n8k16.row.col.f32.f16.f16.f32 "
                 "{%0,%1,%2,%3}, {%4,%5,%6,%7}, {%8,%9}, {%0,%1,%2,%3};"
                 : "+f"(c[0]), "+f"(c[1]), "+f"(c[2]), "+f"(c[3])
                 : "r"(a[0]), "r"(a[1]), "r"(a[2]), "r"(a[3]), "r"(b[0]), "r"(b[1]));
}
__device__ __forceinline__ uint32_t pack_h(float x, float y) {
    __half2 t;
    t.x = __float2half(x);
    t.y = __float2half(y);
    return *(uint32_t*)&t;
}

// ---------------- Scratch (device globals) ----------------
__device__ __align__(256) fp16 g_Xf[(size_t)BSn * HIDn];
__device__ __align__(256) fp16 g_Wqf[(size_t)QDIM * HIDn];
__device__ __align__(256) fp16 g_Wkf[(size_t)KVDIM * HIDn];
__device__ __align__(256) fp16 g_Wvf[(size_t)KVDIM * HIDn];
__device__ __align__(256) fp16 g_Wof[(size_t)HIDn * QDIM];
__device__ __align__(256) fp16 g_Qf[(size_t)BSn * QDIM];
__device__ __align__(256) fp16 g_Kf[(size_t)BSn * KVDIM];
__device__ __align__(256) fp16 g_Vh[(size_t)BSn * KVDIM];
__device__ __align__(256) fp16 g_Vt[(size_t)Bn * KVDIM * Sn];
__device__ __align__(256) fp16 g_Af[(size_t)BSn * QDIM];

// ================= fp16 mma.sync GEMM with fused epilogues =================
// C[M,N] = A[M,K] @ B[N,K]^T  (K-major), 3-stage cp.async, 128x128 tile, BK=32.
// Warp N-mapping uses paired strips {wn*16+sub*8, +64} so RoPE partners
// (d, d+64) are in the same thread's accumulators.
// MODE 0: fp32 out (O-proj).
// MODE 1: fused RMSNorm+RoPE -> fp16 out (Q-proj; tile N = one head).
// MODE 2: z=0 -> norm+rope fp16 (K-proj), z=1 -> plain fp16 (V-proj).
#define PITCHB   80
#define TILE_B   (128 * PITCHB)
#define OFF_A    0
#define OFF_B    (TILE_B)
#define STAGE_B  (2 * TILE_B)          // 20480
#define GSMEM_BYTES (3 * STAGE_B)      // 61440

template <int MODE>
__global__ void __launch_bounds__(256, 2)
gemm_fused(const fp16* __restrict__ A, const fp16* __restrict__ B0,
           const fp16* __restrict__ B1, void* __restrict__ C0v,
           void* __restrict__ C1v, const float* __restrict__ w,
           const float* __restrict__ cosp, const float* __restrict__ sinp,
           int lda, int ldb, int ldc, int K)
{
    extern __shared__ __align__(128) char smem[];
    const int row0 = blockIdx.y * 128;
    const int col0 = blockIdx.x * 128;
    const int zsel = (MODE == 2) ? blockIdx.z : 0;
    const fp16* B = (MODE == 2 && zsel == 1) ? B1 : B0;

    const int tid  = threadIdx.x;
    const int lane = tid & 31;
    const int warp = tid >> 5;
    const int wm   = warp >> 2;
    const int wn   = warp & 3;

    float acc[4][4][4];
    #pragma unroll
    for (int i = 0; i < 4; i++)
        #pragma unroll
        for (int j = 0; j < 4; j++)
            #pragma unroll
            for (int q = 0; q < 4; q++)
                acc[i][j][q] = 0.0f;

    const uint32_t sbase = smem_u32(smem);
    const int nch = K >> 5;

    auto load_stage = [&](int st_idx, int k0) {
        char* st = smem + st_idx * STAGE_B;
        #pragma unroll
        for (int ii = 0; ii < 2; ii++) {
            int i = tid + ii * 256;        // 0..511
            int r = i >> 2, c = i & 3;
            uint32_t dof = (uint32_t)(r * PITCHB + c * 16);
            cp_async16(smem_u32(st + OFF_A + dof), A + (size_t)(row0 + r) * lda + k0 + c * 8);
            cp_async16(smem_u32(st + OFF_B + dof), B + (size_t)(col0 + r) * ldb + k0 + c * 8);
        }
        cp_commit();
    };

    load_stage(0, 0);
    if (nch > 1) load_stage(1, 32);

    int sidx = 0;
    for (int ch = 0; ch < nch; ch++) {
        if (ch + 2 < nch) {
            load_stage((sidx + 2) % 3, (ch + 2) << 5);
            cp_wait<2>();
        } else if (ch + 1 < nch) {
            cp_wait<1>();
        } else {
            cp_wait<0>();
        }
        __syncthreads();

        const uint32_t st = sbase + (uint32_t)(sidx * STAGE_B);

        #pragma unroll
        for (int kk = 0; kk < 32; kk += 16) {
            uint32_t ah[4][4];
            #pragma unroll
            for (int ma = 0; ma < 4; ma++) {
                uint32_t arow = (uint32_t)(wm * 64 + ma * 16 + (lane & 15));
                uint32_t acol = (uint32_t)((kk + ((lane >> 4) << 3)) * 2);
                ldmat4(ah[ma], st + OFF_A + arow * PITCHB + acol);
            }
            uint32_t bb[4][2];
            #pragma unroll
            for (int nb = 0; nb < 2; nb++) {
                // paired-strip mapping: rows [wn*16 + nb*64, +16)
                uint32_t brow = (uint32_t)(wn * 16 + nb * 64 + ((lane >> 4) << 3) + (lane & 7));
                uint32_t bcol = (uint32_t)((kk + (((lane >> 3) & 1) << 3)) * 2);
                uint32_t rh[4];
                ldmat4(rh, st + OFF_B + brow * PITCHB + bcol);
                bb[2 * nb][0] = rh[0]; bb[2 * nb][1] = rh[1];
                bb[2 * nb + 1][0] = rh[2]; bb[2 * nb + 1][1] = rh[3];
            }
            #pragma unroll
            for (int ma = 0; ma < 4; ma++)
                #pragma unroll
                for (int na = 0; na < 4; na++)
                    mma16816(acc[ma][na], ah[ma], bb[na]);
        }
        __syncthreads();
        sidx = (sidx + 1) % 3;
    }

    // column of acc[ma][na]: col0 + wn*16 + (na&1)*8 + (na>>1)*64 + (lane&3)*2
    const bool donorm = (MODE == 1) || (MODE == 2 && zsel == 0);

    if (MODE == 0) {
        float* C = (float*)C0v;
        #pragma unroll
        for (int ma = 0; ma < 4; ma++) {
            int gr = row0 + wm * 64 + ma * 16 + (lane >> 2);
            #pragma unroll
            for (int na = 0; na < 4; na++) {
                int gc = col0 + wn * 16 + (na & 1) * 8 + (na >> 1) * 64 + (lane & 3) * 2;
                float2 v0, v1;
                v0.x = acc[ma][na][0];
                v0.y = acc[ma][na][1];
                v1.x = acc[ma][na][2];
                v1.y = acc[ma][na][3];
                *(float2*)(C + (size_t)gr * ldc + gc)       = v0;
                *(float2*)(C + (size_t)(gr + 8) * ldc + gc) = v1;
            }
        }
    } else if (!donorm) {
        fp16* C = (fp16*)C1v;
        #pragma unroll
        for (int ma = 0; ma < 4; ma++) {
            int gr = row0 + wm * 64 + ma * 16 + (lane >> 2);
            #pragma unroll
            for (int na = 0; na < 4; na++) {
                int gc = col0 + wn * 16 + (na & 1) * 8 + (na >> 1) * 64 + (lane & 3) * 2;
                *(uint32_t*)(C + (size_t)gr * ldc + gc)       = pack_h(acc[ma][na][0], acc[ma][na][1]);
                *(uint32_t*)(C + (size_t)(gr + 8) * ldc + gc) = pack_h(acc[ma][na][2], acc[ma][na][3]);
            }
        }
    } else {
        // ---- fused RMSNorm + RoPE epilogue (tile N = one head of 128) ----
        fp16* C = (fp16*)C0v;
        float* rowsq = (float*)smem;       // 128 floats (stage smem reused)
        if (tid < 128) rowsq[tid] = 0.0f;
        __syncthreads();

        #pragma unroll
        for (int ma = 0; ma < 4; ma++) {
            float p0 = 0.0f, p1 = 0.0f;
            #pragma unroll
            for (int na = 0; na < 4; na++) {
                p0 += acc[ma][na][0] * acc[ma][na][0] + acc[ma][na][1] * acc[ma][na][1];
                p1 += acc[ma][na][2] * acc[ma][na][2] + acc[ma][na][3] * acc[ma][na][3];
            }
            p0 += __shfl_xor_sync(0xFFFFFFFFu, p0, 1);
            p0 += __shfl_xor_sync(0xFFFFFFFFu, p0, 2);
            p1 += __shfl_xor_sync(0xFFFFFFFFu, p1, 1);
            p1 += __shfl_xor_sync(0xFFFFFFFFu, p1, 2);
            if ((lane & 3) == 0) {
                int rl = wm * 64 + ma * 16 + (lane >> 2);
                atomicAdd(&rowsq[rl], p0);
                atomicAdd(&rowsq[rl + 8], p1);
            }
        }
        __syncthreads();

        // weights for this thread's 8 columns (row-independent)
        float wv[2][4];                    // [sub][d, d+1, d+64, d+65]
        #pragma unroll
        for (int sub = 0; sub < 2; sub++) {
            int d = wn * 16 + sub * 8 + (lane & 3) * 2;
            float2 wl = *(const float2*)(w + d);
            float2 wh = *(const float2*)(w + d + 64);
            wv[sub][0] = wl.x; wv[sub][1] = wl.y;
            wv[sub][2] = wh.x; wv[sub][3] = wh.y;
        }

        #pragma unroll
        for (int ma = 0; ma < 4; ma++) {
            int rl = wm * 64 + ma * 16 + (lane >> 2);
            float rn0 = rsqrtf(rowsq[rl]     * (1.0f / 128.0f) + 1e-6f);
            float rn1 = rsqrtf(rowsq[rl + 8] * (1.0f / 128.0f) + 1e-6f);
            #pragma unroll
            for (int half = 0; half < 2; half++) {
                int gr = row0 + rl + half * 8;
                int s  = gr & (Sn - 1);
                float rn = half ? rn1 : rn0;
                const float* cb = cosp + (size_t)s * DHn;
                const float* sb = sinp + (size_t)s * DHn;
                #pragma unroll
                for (int sub = 0; sub < 2; sub++) {
                    int d  = wn * 16 + sub * 8 + (lane & 3) * 2;
                    float x0 = acc[ma][sub][2 * half]     * rn * wv[sub][0];
                    float x1 = acc[ma][sub][2 * half + 1] * rn * wv[sub][1];
                    float y0 = acc[ma][sub + 2][2 * half]     * rn * wv[sub][2];
                    float y1 = acc[ma][sub + 2][2 * half + 1] * rn * wv[sub][3];
                    float2 cl = *(const float2*)(cb + d);
                    float2 ch = *(const float2*)(cb + d + 64);
                    float2 sl = *(const float2*)(sb + d);
                    float2 sh = *(const float2*)(sb + d + 64);
                    float o0 = x0 * cl.x - y0 * sl.x;
                    float o1 = x1 * cl.y - y1 * sl.y;
                    float o2 = y0 * ch.x + x0 * sh.x;
                    float o3 = y1 * ch.y + x1 * sh.y;
                    *(uint32_t*)(C + (size_t)gr * ldc + col0 + d)      = pack_h(o0, o1);
                    *(uint32_t*)(C + (size_t)gr * ldc + col0 + d + 64) = pack_h(o2, o3);
                }
            }
        }
    }
}

// ================= Fused flash attention (single-pass fp16) =================
#define FPITCH 272
#define FT     (128 * FPITCH)          // 34816
#define FOFF_Q 0
#define FOFF_K (FT)
#define FOFF_V (2 * FT)
#define FSMEM_BYTES (3 * FT)           // 104448

__global__ void __launch_bounds__(256, 1)
flash_kernel(const fp16* __restrict__ Qf, const fp16* __restrict__ Kf,
             const fp16* __restrict__ Vf, fp16* __restrict__ Af)
{
    extern __shared__ __align__(128) char smem[];
    const int i    = 15 - blockIdx.x;      // heavy row tiles first
    const int bh   = blockIdx.y;
    const int b    = bh >> 4, h = bh & 15, kv = h >> 2;
    const int row0 = i * 128;
    const int bSn  = b * Sn;
    const int kvoff = kv * DHn;
    const size_t vbase = (size_t)b * KVDIM * Sn;

    const int tid  = threadIdx.x;
    const int lane = tid & 31;
    const int warp = tid >> 5;
    const int w16  = warp * 16;

    const uint32_t sb = smem_u32(smem);
    const uint32_t sQ = sb + FOFF_Q, sK = sb + FOFF_K, sV = sb + FOFF_V;

    auto ldQ = [&]() {
        #pragma unroll
        for (int ii = 0; ii < 8; ii++) {
            int id = tid + ii * 256;
            int r = id >> 4, c = id & 15;
            cp_async16(sQ + (uint32_t)(r * FPITCH + c * 16),
                       Qf + (size_t)(bSn + row0 + r) * QDIM + h * DHn + c * 8);
        }
    };
    auto ldK = [&](int j0) {
        #pragma unroll
        for (int ii = 0; ii < 8; ii++) {
            int id = tid + ii * 256;
            int r = id >> 4, c = id & 15;
            cp_async16(sK + (uint32_t)(r * FPITCH + c * 16),
                       Kf + (size_t)(bSn + j0 + r) * KVDIM + kvoff + c * 8);
        }
    };
    auto ldV = [&](int j0) {
        #pragma unroll
        for (int ii = 0; ii < 8; ii++) {
            int id = tid + ii * 256;
            int r = id >> 4, c = id & 15;
            cp_async16(sV + (uint32_t)(r * FPITCH + c * 16),
                       Vf + vbase + (size_t)(kvoff + r) * Sn + j0 + c * 8);
        }
    };

    float o[16][4];
    #pragma unroll
    for (int nt = 0; nt < 16; nt++)
        #pragma unroll
        for (int q = 0; q < 4; q++) o[nt][q] = 0.0f;
    float m0 = -INFINITY, m1 = -INFINITY, l0 = 0.0f, l1 = 0.0f;

    ldQ();
    ldK(0);
    cp_commit();                       // group: Q + K0

    for (int j = 0; j <= i; j++) {
        const int j0 = j << 7;
        ldV(j0);
        cp_commit();                   // group: V_j
        cp_wait<1>();                  // K_j (and Q) ready
        __syncthreads();

        // ---- S = Q @ K^T ----
        float s[16][4];
        #pragma unroll
        for (int nt = 0; nt < 16; nt++)
            #pragma unroll
            for (int q = 0; q < 4; q++) s[nt][q] = 0.0f;

        #pragma unroll
        for (int kk = 0; kk < 8; kk++) {
            uint32_t aH[4];
            uint32_t aoff = (uint32_t)((w16 + (lane & 15)) * FPITCH +
                                       (kk * 16 + ((lane >> 4) << 3)) * 2);
            ldmat4(aH, sQ + aoff);
            #pragma unroll
            for (int np = 0; np < 8; np++) {
                uint32_t brow = (uint32_t)(np * 16 + ((lane >> 4) << 3) + (lane & 7));
                uint32_t boff = brow * FPITCH +
                                (uint32_t)((kk * 16 + (((lane >> 3) & 1) << 3)) * 2);
                uint32_t rh[4];
                ldmat4(rh, sK + boff);
                uint32_t b0[2] = {rh[0], rh[1]}, b1[2] = {rh[2], rh[3]};
                mma16816(s[2 * np],     aH, b0);
                mma16816(s[2 * np + 1], aH, b1);
            }
        }

        __syncthreads();               // all warps done reading K smem
        if (j < i) ldK(j0 + 128);
        cp_commit();                   // group: K_{j+1}

        // ---- online softmax ----
        const int grow0 = row0 + w16 + (lane >> 2);
        const bool diag = (j == i);
        float nm0 = -INFINITY, nm1 = -INFINITY;
        #pragma unroll
        for (int nt = 0; nt < 16; nt++) {
            #pragma unroll
            for (int q = 0; q < 4; q++) {
                float v = s[nt][q] * SCALE;
                if (diag) {
                    int col = j0 + nt * 8 + (lane & 3) * 2 + (q & 1);
                    int gr = (q < 2) ? grow0 : grow0 + 8;
                    if (col > gr) v = -INFINITY;
                }
                s[nt][q] = v;
            }
            nm0 = fmaxf(nm0, fmaxf(s[nt][0], s[nt][1]));
            nm1 = fmaxf(nm1, fmaxf(s[nt][2], s[nt][3]));
        }
        nm0 = fmaxf(nm0, __shfl_xor_sync(0xFFFFFFFFu, nm0, 1));
        nm0 = fmaxf(nm0, __shfl_xor_sync(0xFFFFFFFFu, nm0, 2));
        nm1 = fmaxf(nm1, __shfl_xor_sync(0xFFFFFFFFu, nm1, 1));
        nm1 = fmaxf(nm1, __shfl_xor_sync(0xFFFFFFFFu, nm1, 2));

        float mn0 = fmaxf(m0, nm0), mn1 = fmaxf(m1, nm1);
        float f0 = (m0 > -1e30f) ? __expf(m0 - mn0) : 0.0f;
        float f1 = (m1 > -1e30f) ? __expf(m1 - mn1) : 0.0f;
        m0 = mn0; m1 = mn1;

        float rs0 = 0.0f, rs1 = 0.0f;
        #pragma unroll
        for (int nt = 0; nt < 16; nt++) {
            float p0 = __expf(s[nt][0] - mn0);
            float p1 = __expf(s[nt][1] - mn0);
            float p2 = __expf(s[nt][2] - mn1);
            float p3 = __expf(s[nt][3] - mn1);
            s[nt][0] = p0; s[nt][1] = p1; s[nt][2] = p2; s[nt][3] = p3;
            rs0 += p0 + p1;
            rs1 += p2 + p3;
        }
        rs0 += __shfl_xor_sync(0xFFFFFFFFu, rs0, 1);
        rs0 += __shfl_xor_sync(0xFFFFFFFFu, rs0, 2);
        rs1 += __shfl_xor_sync(0xFFFFFFFFu, rs1, 1);
        rs1 += __shfl_xor_sync(0xFFFFFFFFu, rs1, 2);
        l0 = l0 * f0 + rs0;
        l1 = l1 * f1 + rs1;
        #pragma unroll
        for (int nt = 0; nt < 16; nt++) {
            o[nt][0] *= f0; o[nt][1] *= f0;
            o[nt][2] *= f1; o[nt][3] *= f1;
        }

        cp_wait<1>();                  // V_j ready
        __syncthreads();

        // ---- O += P @ V ----
        #pragma unroll
        for (int kk = 0; kk < 8; kk++) {
            uint32_t pH[4];
            pH[0] = pack_h(s[2 * kk][0],     s[2 * kk][1]);
            pH[1] = pack_h(s[2 * kk][2],     s[2 * kk][3]);
            pH[2] = pack_h(s[2 * kk + 1][0], s[2 * kk + 1][1]);
            pH[3] = pack_h(s[2 * kk + 1][2], s[2 * kk + 1][3]);
            #pragma unroll
            for (int np = 0; np < 8; np++) {
                uint32_t brow = (uint32_t)(np * 16 + ((lane >> 4) << 3) + (lane & 7));
                uint32_t boff = brow * FPITCH +
                                (uint32_t)((kk * 16 + (((lane >> 3) & 1) << 3)) * 2);
                uint32_t rh[4];
                ldmat4(rh, sV + boff);
                uint32_t b0[2] = {rh[0], rh[1]}, b1[2] = {rh[2], rh[3]};
                mma16816(o[2 * np],     pH, b0);
                mma16816(o[2 * np + 1], pH, b1);
            }
        }
        __syncthreads();               // all warps done reading V smem
    }

    // ---- epilogue: out = O / l -> fp16 ----
    const float inv0 = 1.0f / l0, inv1 = 1.0f / l1;
    const int gr0 = bSn + row0 + w16 + (lane >> 2);
    const size_t cbase = (size_t)h * DHn + (lane & 3) * 2;
    #pragma unroll
    for (int nt = 0; nt < 16; nt++) {
        size_t i0 = (size_t)gr0 * QDIM + cbase + nt * 8;
        size_t i1 = (size_t)(gr0 + 8) * QDIM + cbase + nt * 8;
        *(uint32_t*)(Af + i0) = pack_h(o[nt][0] * inv0, o[nt][1] * inv0);
        *(uint32_t*)(Af + i1) = pack_h(o[nt][2] * inv1, o[nt][3] * inv1);
    }
}

// ---------------- Elementwise cast f32 -> fp16 ----------------
__global__ void cast_plain(const float* __restrict__ x, fp16* __restrict__ y, int n)
{
    for (int i = blockIdx.x * blockDim.x + threadIdx.x; i < n; i += gridDim.x * blockDim.x)
        y[i] = __float2half(x[i]);
}

// ---------------- Transpose: src[R,C] f32 -> dst[C,R] fp16 ----------------
__global__ void half_transpose(const float* __restrict__ src, fp16* __restrict__ dst,
                               int R, int C, long sS, long sD)
{
    __shared__ float t[32][33];
    src += (size_t)blockIdx.z * sS;
    dst += (size_t)blockIdx.z * sD;
    int c0 = blockIdx.x * 32, r0 = blockIdx.y * 32;
    int tx = threadIdx.x, ty = threadIdx.y;
    #pragma unroll
    for (int i = 0; i < 4; i++)
        t[ty + i * 8][tx] = src[(size_t)(r0 + ty + i * 8) * C + c0 + tx];
    __syncthreads();
    #pragma unroll
    for (int i = 0; i < 4; i++)
        dst[(size_t)(c0 + ty + i * 8) * R + r0 + tx] = __float2half(t[tx][ty + i * 8]);
}

// ---------------- Transpose: src[R,C] fp16 -> dst[C,R] fp16 ----------------
__global__ void half_transpose_h(const fp16* __restrict__ src, fp16* __restrict__ dst,
                                 int R, int C, long sS, long sD)
{
    __shared__ fp16 t[32][34];
    src += (size_t)blockIdx.z * sS;
    dst += (size_t)blockIdx.z * sD;
    int c0 = blockIdx.x * 32, r0 = blockIdx.y * 32;
    int tx = threadIdx.x, ty = threadIdx.y;
    #pragma unroll
    for (int i = 0; i < 4; i++)
        t[ty + i * 8][tx] = src[(size_t)(r0 + ty + i * 8) * C + c0 + tx];
    __syncthreads();
    #pragma unroll
    for (int i = 0; i < 4; i++)
        dst[(size_t)(c0 + ty + i * 8) * R + r0 + tx] = t[tx][ty + i * 8];
}

// ---------------- Launch ----------------
extern "C" void kernel_launch(void* const* d_in, const int* in_sizes, int n_in,
                              void* d_out, int out_size)
{
    (void)in_sizes; (void)n_in; (void)out_size;
    const float* X    = (const float*)d_in[0];
    const float* cosp = (const float*)d_in[2];
    const float* sinp = (const float*)d_in[3];
    const float* Wq   = (const float*)d_in[4];
    const float* Wk   = (const float*)d_in[5];
    const float* Wv   = (const float*)d_in[6];
    const float* Wo   = (const float*)d_in[7];
    const float* qw   = (const float*)d_in[8];
    const float* kw   = (const float*)d_in[9];
    float* out = (float*)d_out;

    cudaFuncSetAttribute(gemm_fused<0>, cudaFuncAttributeMaxDynamicSharedMemorySize, GSMEM_BYTES);
    cudaFuncSetAttribute(gemm_fused<1>, cudaFuncAttributeMaxDynamicSharedMemorySize, GSMEM_BYTES);
    cudaFuncSetAttribute(gemm_fused<2>, cudaFuncAttributeMaxDynamicSharedMemorySize, GSMEM_BYTES);
    cudaFuncSetAttribute(flash_kernel, cudaFuncAttributeMaxDynamicSharedMemorySize, FSMEM_BYTES);

    void *p;
    #define SYM(v, s) cudaGetSymbolAddress(&p, s); auto v = (decltype(&s[0]))p;
    SYM(Xf, g_Xf)
    SYM(Wqf, g_Wqf) SYM(Wkf, g_Wkf) SYM(Wvf, g_Wvf) SYM(Wof, g_Wof)
    SYM(Qf, g_Qf)  SYM(Kf, g_Kf)  SYM(Vh, g_Vh)  SYM(Vt, g_Vt)  SYM(Af, g_Af)
    #undef SYM

    // 0) X -> fp16;  weights -> transposed fp16 [N,K]
    cast_plain<<<2048, 256>>>(X, Xf, BSn * HIDn);
    half_transpose<<<dim3(QDIM / 32, HIDn / 32, 1), dim3(32, 8)>>>(Wq, Wqf, HIDn, QDIM, 0, 0);
    half_transpose<<<dim3(KVDIM / 32, HIDn / 32, 1), dim3(32, 8)>>>(Wk, Wkf, HIDn, KVDIM, 0, 0);
    half_transpose<<<dim3(KVDIM / 32, HIDn / 32, 1), dim3(32, 8)>>>(Wv, Wvf, HIDn, KVDIM, 0, 0);
    half_transpose<<<dim3(HIDn / 32, QDIM / 32, 1), dim3(32, 8)>>>(Wo, Wof, QDIM, HIDn, 0, 0);

    // 1) Q projection + fused RMSNorm/RoPE -> fp16 Qf
    gemm_fused<1><<<dim3(QDIM / 128, BSn / 128), 256, GSMEM_BYTES>>>(
        Xf, Wqf, (const fp16*)0, Qf, (void*)0, qw, cosp, sinp, HIDn, HIDn, QDIM, HIDn);

    // 2) K projection (+norm/rope) and V projection (plain fp16), merged launch
    gemm_fused<2><<<dim3(KVDIM / 128, BSn / 128, 2), 256, GSMEM_BYTES>>>(
        Xf, Wkf, Wvf, Kf, Vh, kw, cosp, sinp, HIDn, HIDn, KVDIM, HIDn);

    // 3) V -> transposed [b][kv*dh][s] (fp16 -> fp16)
    half_transpose_h<<<dim3(KVDIM / 32, Sn / 32, Bn), dim3(32, 8)>>>(
        Vh, Vt, Sn, KVDIM, (long)Sn * KVDIM, (long)KVDIM * Sn);

    // 4) Fused flash attention -> fp16 output
    flash_kernel<<<dim3(Sn / 128, Bn * NHn), 256, FSMEM_BYTES>>>(Qf, Kf, Vt, Af);

    // 5) Output projection (fp32 out)
    gemm_fused<0><<<dim3(HIDn / 128, BSn / 128), 256, GSMEM_BYTES>>>(
        Af, Wof, (const fp16*)0, out, (void*)0, (const float*)0, (const float*)0,
        (const float*)0, QDIM, QDIM, HIDn, QDIM);
}